// round 13
// baseline (speedup 1.0000x reference)
#include <cuda_runtime.h>
#include <math.h>

static constexpr int NPTS = 500000;
static constexpr int NVOX = 1 << 24;       // 256^3
static constexpr int NH   = 136;           // compact k2 width (17 chunks of 8)
static constexpr int NHVOX = 256 * 256 * NH;

__device__ float2 gA[NVOX];    // scatter target: ras_x + i*ras_y
__device__ float2 gX[NHVOX];   // N^x spectrum (axes 2 then 1), compact k2<=135
__device__ float2 gY[NHVOX];   // N^y spectrum (axis 2), merged into gW at axis-1
__device__ float2 gW[NHVOX];   // w2*N^z -> += w1*N^y -> S -> Phi partial inverse
__device__ float  gZ[NVOX];    // ras_z (real) in; phi (real) out
__device__ double g_accum;

// ---------------------------------------------------------------------------
__device__ __forceinline__ void corner_setup(float v, int& i0, int& i1, float& f) {
    float x  = v * 256.0f;
    float fl = floorf(x);
    i0 = (int)fl;
    f  = x - fl;
    i1 = (i0 + 1) & 255;
}

// ---------------------------------------------------------------------------
__global__ void __launch_bounds__(256) scatter_kernel(const float* __restrict__ V,
                                                      const float* __restrict__ N) {
    int p = blockIdx.x * 256 + threadIdx.x;
    if (p >= NPTS) return;
    float vx = V[3 * p + 0], vy = V[3 * p + 1], vz = V[3 * p + 2];
    float nx = N[3 * p + 0], ny = N[3 * p + 1], nz = N[3 * p + 2];

    int ix0, ix1, iy0, iy1, iz0, iz1;
    float fx, fy, fz;
    corner_setup(vx, ix0, ix1, fx);
    corner_setup(vy, iy0, iy1, fy);
    corner_setup(vz, iz0, iz1, fz);

    float wx[2] = {1.0f - fx, fx};
    float wy[2] = {1.0f - fy, fy};
    float wz[2] = {1.0f - fz, fz};
    int ix[2] = {ix0, ix1}, iy[2] = {iy0, iy1}, iz[2] = {iz0, iz1};

#pragma unroll
    for (int c = 0; c < 8; c++) {
        int b0 = (c >> 2) & 1, b1 = (c >> 1) & 1, b2 = c & 1;
        int lin = (((ix[b0] << 8) | iy[b1]) << 8) | iz[b2];
        float w = wx[b0] * wy[b1] * wz[b2];
        asm volatile("red.global.add.v2.f32 [%0], {%1, %2};"
                     :: "l"(&gA[lin]), "f"(w * nx), "f"(w * ny) : "memory");
        atomicAdd(&gZ[lin], w * nz);
    }
}

// ---------------------------------------------------------------------------
// Warp-level 256-pt FFT: 8 complex per thread.
// Input: reg j holds x[32*br3(j)+lane]. Output: lane holds X[j + 8*br5(lane)].
// ---------------------------------------------------------------------------
__device__ __forceinline__ void xstage(float (&ar)[8], float (&ai)[8], int lane, int h,
                                       float twr_in, float twi_in) {
    const bool up = (lane & h) != 0;
    const float s  = up ? -1.0f : 1.0f;
    const float tr = up ? twr_in : 1.0f;
    const float ti = up ? twi_in : 0.0f;
#pragma unroll
    for (int k = 0; k < 8; k++) {
        float orr = __shfl_xor_sync(0xffffffffu, ar[k], h);
        float ori = __shfl_xor_sync(0xffffffffu, ai[k], h);
        float dr = fmaf(s, ar[k], orr);
        float di = fmaf(s, ai[k], ori);
        ar[k] = dr * tr - di * ti;
        ai[k] = dr * ti + di * tr;
    }
}

template <int DIR>
__device__ __forceinline__ void warp_fft256_reg(float (&ar)[8], float (&ai)[8], int lane) {
    const float D = (float)DIR;
    const float C = 0.70710678118654752440f;
    float tr, ti;

#pragma unroll
    for (int p = 0; p < 8; p += 2) {
        tr = ar[p + 1]; ti = ai[p + 1];
        ar[p + 1] = ar[p] - tr;  ai[p + 1] = ai[p] - ti;
        ar[p] += tr;             ai[p] += ti;
    }
#pragma unroll
    for (int q = 0; q < 8; q += 4) {
        tr = ar[q + 2]; ti = ai[q + 2];
        ar[q + 2] = ar[q] - tr;  ai[q + 2] = ai[q] - ti;
        ar[q] += tr;             ai[q] += ti;
        tr = -D * ai[q + 3];     ti = D * ar[q + 3];
        ar[q + 3] = ar[q + 1] - tr;  ai[q + 3] = ai[q + 1] - ti;
        ar[q + 1] += tr;             ai[q + 1] += ti;
    }
    tr = ar[4]; ti = ai[4];
    ar[4] = ar[0] - tr; ai[4] = ai[0] - ti; ar[0] += tr; ai[0] += ti;
    tr = C * (ar[5] - D * ai[5]); ti = C * (ai[5] + D * ar[5]);
    ar[5] = ar[1] - tr; ai[5] = ai[1] - ti; ar[1] += tr; ai[1] += ti;
    tr = -D * ai[6]; ti = D * ar[6];
    ar[6] = ar[2] - tr; ai[6] = ai[2] - ti; ar[2] += tr; ai[2] += ti;
    tr = -C * (ar[7] + D * ai[7]); ti = C * (D * ar[7] - ai[7]);
    ar[7] = ar[3] - tr; ai[7] = ai[3] - ti; ar[3] += tr; ai[3] += ti;

    float w1r, w1i;
    __sincosf(D * 0.024543692606170259f * (float)lane, &w1i, &w1r);   // 2*pi/256
    float wr = w1r, wi = w1i;
#pragma unroll
    for (int k = 1; k < 8; k++) {
        tr = ar[k] * wr - ai[k] * wi;
        ai[k] = ar[k] * wi + ai[k] * wr;
        ar[k] = tr;
        if (k < 7) { float nr = wr * w1r - wi * w1i; wi = wr * w1i + wi * w1r; wr = nr; }
    }

    float s16r, s16i, s8r, s8i, s4r, s4i;
    __sincosf(D * 0.19634954084936207f * (float)(lane & 15), &s16i, &s16r);  // pi/16
    __sincosf(D * 0.39269908169872414f * (float)(lane & 7),  &s8i,  &s8r);   // pi/8
    __sincosf(D * 0.78539816339744831f * (float)(lane & 3),  &s4i,  &s4r);   // pi/4
    xstage(ar, ai, lane, 16, s16r, s16i);
    xstage(ar, ai, lane, 8,  s8r,  s8i);
    xstage(ar, ai, lane, 4,  s4r,  s4i);
    xstage(ar, ai, lane, 2, (lane & 1) ? 0.0f : 1.0f, (lane & 1) ? D : 0.0f);
    xstage(ar, ai, lane, 1, 1.0f, 0.0f);
}

// smem address map for a 256-entry line: addr(k) = 9*(k>>3) + (k&7)
__device__ __forceinline__ int lmap(int k) { return 9 * (k >> 3) + (k & 7); }

// ---------------------------------------------------------------------------
// A axis-2 pass + Hermitian channel split into compact gX, gY (k2 <= 135).
// ---------------------------------------------------------------------------
__global__ void __launch_bounds__(256) fft_axis2_split(const float2* __restrict__ A,
                                                       float2* __restrict__ X,
                                                       float2* __restrict__ Y) {
    __shared__ float s_re[8][288];
    __shared__ float s_im[8][288];
    int w = threadIdx.x >> 5, lane = threadIdx.x & 31;
    int line = blockIdx.x * 8 + w;
    int ibase = line * 256;
    int obase = line * NH;

    float ar[8], ai[8];
    const int br3[8] = {0, 4, 2, 6, 1, 5, 3, 7};
#pragma unroll
    for (int t = 0; t < 8; t++) {
        float2 v = A[ibase + 32 * br3[t] + lane];
        ar[t] = v.x; ai[t] = v.y;
    }
    warp_fft256_reg<-1>(ar, ai, lane);

    int m = (int)(__brev((unsigned)lane) >> 27);
#pragma unroll
    for (int t = 0; t < 8; t++) {
        s_re[w][9 * m + t] = ar[t];
        s_im[w][9 * m + t] = ai[t];
    }
    __syncwarp();

#pragma unroll
    for (int t = 0; t < 5; t++) {
        int k = lane + 32 * t;
        if (t < 4 || lane < 8) {
            int km = (256 - k) & 255;
            float ur = s_re[w][lmap(k)],  ui = s_im[w][lmap(k)];
            float vr = s_re[w][lmap(km)], vi = s_im[w][lmap(km)];
            X[obase + k] = make_float2(0.5f * (ur + vr),  0.5f * (ui - vi));
            Y[obase + k] = make_float2(0.5f * (ui + vi), -0.5f * (ur - vr));
        }
    }
}

// ---------------------------------------------------------------------------
// z-channel axis-2 forward R2C into compact gW, PRE-MULTIPLIED by w2(k2).
// ---------------------------------------------------------------------------
__global__ void __launch_bounds__(256) fft_axis2_r2c_w2(const float* __restrict__ in,
                                                        float2* __restrict__ g) {
    __shared__ float s_re[8][288];
    __shared__ float s_im[8][288];
    int w = threadIdx.x >> 5, lane = threadIdx.x & 31;
    int pj = blockIdx.x * 8 + w;
    int i0 = pj >> 7, j = pj & 127;
    int la = (i0 << 16) | (j << 9);
    int lb = la + 256;
    int oa = (i0 * 256 + 2 * j) * NH;
    int ob = oa + NH;

    float ar[8], ai[8];
    const int br3[8] = {0, 4, 2, 6, 1, 5, 3, 7};
#pragma unroll
    for (int t = 0; t < 8; t++) {
        int idx = 32 * br3[t] + lane;
        ar[t] = in[la + idx];
        ai[t] = in[lb + idx];
    }
    warp_fft256_reg<-1>(ar, ai, lane);

    int m = (int)(__brev((unsigned)lane) >> 27);
#pragma unroll
    for (int t = 0; t < 8; t++) {
        s_re[w][9 * m + t] = ar[t];
        s_im[w][9 * m + t] = ai[t];
    }
    __syncwarp();

#pragma unroll
    for (int t = 0; t < 5; t++) {
        int k = lane + 32 * t;
        if (t < 4 || lane < 8) {
            int km = (256 - k) & 255;
            float w2 = (float)(k - ((k >= 128) ? 256 : 0));
            float ur = s_re[w][lmap(k)],  ui = s_im[w][lmap(k)];
            float vr = s_re[w][lmap(km)], vi = s_im[w][lmap(km)];
            g[oa + k] = make_float2(w2 * 0.5f * (ur + vr),  w2 * 0.5f * (ui - vi));
            g[ob + k] = make_float2(w2 * 0.5f * (ui + vi), -w2 * 0.5f * (ur - vr));
        }
    }
}

// ---------------------------------------------------------------------------
// axis-2 inverse C2R: compact Hermitian lines -> real full-stride lines.
// ---------------------------------------------------------------------------
__global__ void __launch_bounds__(256) fft_axis2_c2r(const float2* __restrict__ g,
                                                     float* __restrict__ outr) {
    __shared__ float s_re[8][288];
    __shared__ float s_im[8][288];
    int w = threadIdx.x >> 5, lane = threadIdx.x & 31;
    int pj = blockIdx.x * 8 + w;
    int i0 = pj >> 7, j = pj & 127;
    int la = (i0 << 16) | (j << 9);
    int lb = la + 256;
    int oa = (i0 * 256 + 2 * j) * NH;
    int ob = oa + NH;

#pragma unroll
    for (int t = 0; t < 5; t++) {
        int k = lane + 32 * t;
        if (t < 4 || lane == 0) {             // k <= 128
            float2 Ha = g[oa + k];
            float2 Hb = g[ob + k];
            s_re[w][lmap(k)] = Ha.x - Hb.y;
            s_im[w][lmap(k)] = Ha.y + Hb.x;
            if (k >= 1 && k <= 127) {
                s_re[w][lmap(256 - k)] = Ha.x + Hb.y;
                s_im[w][lmap(256 - k)] = Hb.x - Ha.y;
            }
        }
    }
    __syncwarp();

    float ar[8], ai[8];
    const int br3[8] = {0, 4, 2, 6, 1, 5, 3, 7};
#pragma unroll
    for (int t = 0; t < 8; t++) {
        int idx = 32 * br3[t] + lane;
        ar[t] = s_re[w][lmap(idx)];
        ai[t] = s_im[w][lmap(idx)];
    }
    warp_fft256_reg<1>(ar, ai, lane);

    int obp = 8 * (int)(__brev((unsigned)lane) >> 27);
    float4* pa = (float4*)(outr + la + obp);
    float4* pb = (float4*)(outr + lb + obp);
    pa[0] = make_float4(ar[0], ar[1], ar[2], ar[3]);
    pa[1] = make_float4(ar[4], ar[5], ar[6], ar[7]);
    pb[0] = make_float4(ai[0], ai[1], ai[2], ai[3]);
    pb[1] = make_float4(ai[4], ai[5], ai[6], ai[7]);
}

// ---------------------------------------------------------------------------
// Strided-axis pass (compact volumes). blockIdx.y = outer, blockIdx.x = chunk.
// ---------------------------------------------------------------------------
template <int DIR>
__global__ void __launch_bounds__(256) fft_strided_reg(float2* __restrict__ g,
                                                       int S, int outerStride) {
    __shared__ float s_re[2304];
    __shared__ float s_im[2304];

    int tid  = threadIdx.x;
    int base = blockIdx.y * outerStride + blockIdx.x * 8;

#pragma unroll
    for (int it = 0; it < 8; it++) {
        int e = it * 256 + tid;
        int r = e >> 3, c = e & 7;
        float2 v = g[base + r * S + c];
        int a = 9 * r + (c ^ ((r >> 5) & 7));
        s_re[a] = v.x; s_im[a] = v.y;
    }
    __syncthreads();

    int w = tid >> 5, lane = tid & 31;
    float ar[8], ai[8];
    const int br3[8] = {0, 4, 2, 6, 1, 5, 3, 7};
#pragma unroll
    for (int j = 0; j < 8; j++) {
        int r = 32 * br3[j] + lane;
        int a = 9 * r + (w ^ ((r >> 5) & 7));
        ar[j] = s_re[a]; ai[j] = s_im[a];
    }

    warp_fft256_reg<DIR>(ar, ai, lane);
    __syncthreads();

    int k2 = (int)(__brev((unsigned)lane) >> 27);
#pragma unroll
    for (int k1 = 0; k1 < 8; k1++) {
        int r = k1 + 8 * k2;
        int a = 9 * r + (w ^ ((r >> 5) & 7));
        s_re[a] = ar[k1]; s_im[a] = ai[k1];
    }
    __syncthreads();

#pragma unroll
    for (int it = 0; it < 8; it++) {
        int e = it * 256 + tid;
        int r = e >> 3, c = e & 7;
        int a = 9 * r + (c ^ ((r >> 5) & 7));
        float2 v;
        v.x = s_re[a]; v.y = s_im[a];
        g[base + r * S + c] = v;
    }
}

// ---------------------------------------------------------------------------
// Axis-1 MERGE pass: forward-FFT the Y tile along axis 1, scale each output
// row r (= k1) by w1(k1), and ADD into gW (already axis-1 transformed, holding
// w2*W^). gY is dead after this pass.
// ---------------------------------------------------------------------------
__global__ void __launch_bounds__(256) fft_strided_merge(const float2* __restrict__ src,
                                                         float2* __restrict__ dst,
                                                         int S, int outerStride) {
    __shared__ float s_re[2304];
    __shared__ float s_im[2304];

    int tid  = threadIdx.x;
    int base = blockIdx.y * outerStride + blockIdx.x * 8;

#pragma unroll
    for (int it = 0; it < 8; it++) {
        int e = it * 256 + tid;
        int r = e >> 3, c = e & 7;
        float2 v = src[base + r * S + c];
        int a = 9 * r + (c ^ ((r >> 5) & 7));
        s_re[a] = v.x; s_im[a] = v.y;
    }
    __syncthreads();

    int w = tid >> 5, lane = tid & 31;
    float ar[8], ai[8];
    const int br3[8] = {0, 4, 2, 6, 1, 5, 3, 7};
#pragma unroll
    for (int j = 0; j < 8; j++) {
        int r = 32 * br3[j] + lane;
        int a = 9 * r + (w ^ ((r >> 5) & 7));
        ar[j] = s_re[a]; ai[j] = s_im[a];
    }

    warp_fft256_reg<-1>(ar, ai, lane);
    __syncthreads();

    int k2 = (int)(__brev((unsigned)lane) >> 27);
#pragma unroll
    for (int j = 0; j < 8; j++) {
        int r = j + 8 * k2;                     // output row = k1
        float w1 = (float)(r - ((r >= 128) ? 256 : 0));
        int a = 9 * r + (w ^ ((r >> 5) & 7));
        s_re[a] = w1 * ar[j]; s_im[a] = w1 * ai[j];
    }
    __syncthreads();

#pragma unroll
    for (int it = 0; it < 8; it++) {
        int e = it * 256 + tid;
        int r = e >> 3, c = e & 7;
        int a = 9 * r + (c ^ ((r >> 5) & 7));
        float2 v = dst[base + r * S + c];
        v.x += s_re[a]; v.y += s_im[a];
        dst[base + r * S + c] = v;
    }
}

// ---------------------------------------------------------------------------
// FUSED v4 (v1 structure, 2 channels): forward axis-0 FFT of S (=gW holding
// w1*Y^+w2*W^, axes 2,1 done) and of X^; combine D = w0*X^ + S^; inverse
// axis-0 FFT of Phi; store to gW. blockIdx.y = k1, blockIdx.x = k2 chunk t2.
// ---------------------------------------------------------------------------
__global__ void __launch_bounds__(256) fused_axis0_combine_v4() {
    __shared__ float sX_re[2304], sX_im[2304];
    __shared__ float sS_re[2304], sS_im[2304];

    int tid  = threadIdx.x;
    int k1   = blockIdx.y;
    int t2   = blockIdx.x;
    int cbase = k1 * NH + t2 * 8;

    // Load X and S tiles up front (overlapped global loads, v1 style).
#pragma unroll
    for (int it = 0; it < 8; it++) {
        int e = it * 256 + tid;
        int r = e >> 3, c = e & 7;
        int a = 9 * r + (c ^ ((r >> 5) & 7));
        int gi = r * (256 * NH) + cbase + c;
        float2 vx = gX[gi];
        sX_re[a] = vx.x; sX_im[a] = vx.y;
        float2 vs = gW[gi];
        sS_re[a] = vs.x; sS_im[a] = vs.y;
    }
    __syncthreads();

    int w = tid >> 5, lane = tid & 31;
    const int br3[8] = {0, 4, 2, 6, 1, 5, 3, 7};
    int k2r = (int)(__brev((unsigned)lane) >> 27);
    float ar[8], ai[8];

    // Forward axis-0 FFT on X column w (column-private per warp).
#pragma unroll
    for (int j = 0; j < 8; j++) {
        int r = 32 * br3[j] + lane;
        int a = 9 * r + (w ^ ((r >> 5) & 7));
        ar[j] = sX_re[a]; ai[j] = sX_im[a];
    }
    warp_fft256_reg<-1>(ar, ai, lane);
#pragma unroll
    for (int k = 0; k < 8; k++) {
        int r = k + 8 * k2r;
        int a = 9 * r + (w ^ ((r >> 5) & 7));
        sX_re[a] = ar[k]; sX_im[a] = ai[k];
    }
    __syncwarp();

    // Forward axis-0 FFT on S column w.
#pragma unroll
    for (int j = 0; j < 8; j++) {
        int r = 32 * br3[j] + lane;
        int a = 9 * r + (w ^ ((r >> 5) & 7));
        ar[j] = sS_re[a]; ai[j] = sS_im[a];
    }
    warp_fft256_reg<-1>(ar, ai, lane);
#pragma unroll
    for (int k = 0; k < 8; k++) {
        int r = k + 8 * k2r;
        int a = 9 * r + (w ^ ((r >> 5) & 7));
        sS_re[a] = ar[k]; sS_im[a] = ai[k];
    }
    __syncthreads();

    // Elementwise spectral combine: Phi overwrites sX in place.
    float w1c = (float)(k1 - ((k1 >= 128) ? 256 : 0));
#pragma unroll
    for (int it = 0; it < 8; it++) {
        int e = it * 256 + tid;
        int r = e >> 3, c = e & 7;
        int a = 9 * r + (c ^ ((r >> 5) & 7));

        int k0 = r, k2 = 8 * t2 + c;
        float w0 = (float)(k0 - ((k0 >= 128) ? 256 : 0));
        float w2 = (float)(k2 - ((k2 >= 128) ? 256 : 0));

        float Dr = fmaf(w0, sX_re[a], sS_re[a]);
        float Di = fmaf(w0, sX_im[a], sS_im[a]);

        float s = w0 * w0 + w1c * w1c + w2 * w2;
        float G = expf(s * (-200.0f / 65536.0f));
        float denom = -39.478417604357434f * s + 1e-6f;
        float f = (6.283185307179586f * G / denom) * (1.0f / 16777216.0f);

        float pr = Di * f;
        float pi = -Dr * f;
        if ((r | k1 | t2 | c) == 0) { pr = 0.0f; pi = 0.0f; }

        sX_re[a] = pr; sX_im[a] = pi;
    }
    __syncthreads();

    // Inverse axis-0 FFT on Phi column w.
#pragma unroll
    for (int j = 0; j < 8; j++) {
        int r = 32 * br3[j] + lane;
        int a = 9 * r + (w ^ ((r >> 5) & 7));
        ar[j] = sX_re[a]; ai[j] = sX_im[a];
    }
    warp_fft256_reg<1>(ar, ai, lane);
    __syncthreads();
#pragma unroll
    for (int j = 0; j < 8; j++) {
        int r = j + 8 * k2r;
        int a = 9 * r + (w ^ ((r >> 5) & 7));
        sX_re[a] = ar[j]; sX_im[a] = ai[j];
    }
    __syncthreads();

#pragma unroll
    for (int it = 0; it < 8; it++) {
        int e = it * 256 + tid;
        int r = e >> 3, c = e & 7;
        int a = 9 * r + (c ^ ((r >> 5) & 7));
        float2 v;
        v.x = sX_re[a]; v.y = sX_im[a];
        gW[r * (256 * NH) + cbase + c] = v;
    }
}

// ---------------------------------------------------------------------------
__global__ void __launch_bounds__(256) interp_kernel(const float* __restrict__ V) {
    int p = blockIdx.x * 256 + threadIdx.x;
    float val = 0.0f;
    if (p < NPTS) {
        float vx = V[3 * p + 0], vy = V[3 * p + 1], vz = V[3 * p + 2];
        int ix0, ix1, iy0, iy1, iz0, iz1;
        float fx, fy, fz;
        corner_setup(vx, ix0, ix1, fx);
        corner_setup(vy, iy0, iy1, fy);
        corner_setup(vz, iz0, iz1, fz);
        float wx[2] = {1.0f - fx, fx};
        float wy[2] = {1.0f - fy, fy};
        float wz[2] = {1.0f - fz, fz};
        int ix[2] = {ix0, ix1}, iy[2] = {iy0, iy1}, iz[2] = {iz0, iz1};
#pragma unroll
        for (int c = 0; c < 8; c++) {
            int b0 = (c >> 2) & 1, b1 = (c >> 1) & 1, b2 = c & 1;
            int lin = (((ix[b0] << 8) | iy[b1]) << 8) | iz[b2];
            val += wx[b0] * wy[b1] * wz[b2] * gZ[lin];
        }
    }
    __shared__ float red[256];
    red[threadIdx.x] = val;
    __syncthreads();
#pragma unroll
    for (int off = 128; off > 0; off >>= 1) {
        if (threadIdx.x < off) red[threadIdx.x] += red[threadIdx.x + off];
        __syncthreads();
    }
    if (threadIdx.x == 0) atomicAdd(&g_accum, (double)red[0]);
}

// ---------------------------------------------------------------------------
__global__ void __launch_bounds__(256) final_kernel(float* __restrict__ out) {
    int idx = blockIdx.x * 256 + threadIdx.x;
    float mean = (float)(g_accum * (1.0 / (double)NPTS));
    float f0 = gZ[0] - mean;
    float sc = -0.5f / fabsf(f0);
    out[idx] = (gZ[idx] - mean) * sc;
}

// ---------------------------------------------------------------------------
extern "C" void kernel_launch(void* const* d_in, const int* in_sizes, int n_in,
                              void* d_out, int out_size) {
    const float* V  = (const float*)d_in[0];
    const float* Np = (const float*)d_in[1];
    float* out = (float*)d_out;

    void *pA, *pX, *pY, *pW, *pZ, *pAcc;
    cudaGetSymbolAddress(&pA, gA);
    cudaGetSymbolAddress(&pX, gX);
    cudaGetSymbolAddress(&pY, gY);
    cudaGetSymbolAddress(&pW, gW);
    cudaGetSymbolAddress(&pZ, gZ);
    cudaGetSymbolAddress(&pAcc, g_accum);

    cudaMemsetAsync(pA, 0, (size_t)NVOX * sizeof(float2));
    cudaMemsetAsync(pZ, 0, (size_t)NVOX * sizeof(float));
    cudaMemsetAsync(pAcc, 0, sizeof(double));

    const int PB = (NPTS + 255) / 256;

    scatter_kernel<<<PB, 256>>>(V, Np);

    dim3 gHalf(17, 256);
    const int S1 = NH;
    const int O1 = 256 * NH;

    // x,y channels: axis-2 FFT + Hermitian split into compact gX, gY
    fft_axis2_split<<<8192, 256>>>((const float2*)pA, (float2*)pX, (float2*)pY);

    // z channel: R2C axis 2 (pre-multiplied by w2) -> compact gW, then axis 1
    fft_axis2_r2c_w2<<<4096, 256>>>((const float*)pZ, (float2*)pW);
    fft_strided_reg<-1><<<gHalf, 256>>>((float2*)pW, S1, O1);       // W axis 1

    // Y axis 1 merged into gW with w1 scaling (gY dead afterwards)
    fft_strided_merge<<<gHalf, 256>>>((const float2*)pY, (float2*)pW, S1, O1);

    // X axis 1
    fft_strided_reg<-1><<<gHalf, 256>>>((float2*)pX, S1, O1);

    // fused: fwd axis-0 of X and S + combine + inverse axis-0 of Phi
    fused_axis0_combine_v4<<<gHalf, 256>>>();

    // inverse axis 1, then C2R axis 2 into gZ
    fft_strided_reg<1><<<gHalf, 256>>>((float2*)pW, S1, O1);
    fft_axis2_c2r<<<4096, 256>>>((const float2*)pW, (float*)pZ);

    interp_kernel<<<PB, 256>>>(V);
    final_kernel<<<65536, 256>>>(out);
}

// round 14
// speedup vs baseline: 1.3760x; 1.3760x over previous
#include <cuda_runtime.h>
#include <math.h>

static constexpr int NPTS = 500000;
static constexpr int NVOX = 1 << 24;       // 256^3
static constexpr int NH   = 136;           // compact k2 width (17 chunks of 8)
static constexpr int NHVOX = 256 * 256 * NH;

__device__ float2 gA[NVOX];    // scatter target: ras_x + i*ras_y
__device__ float2 gX[NHVOX];   // N^x spectrum (axes 2 then 1), compact k2<=135
__device__ float2 gY[NHVOX];   // N^y spectrum, compact
__device__ float2 gW[NHVOX];   // N^z spectrum (axes 2,1) -> Phi -> partial inverse
__device__ float  gZ[NVOX];    // ras_z (real) in; phi (real) out
__device__ double g_accum;

// ---------------------------------------------------------------------------
__device__ __forceinline__ void corner_setup(float v, int& i0, int& i1, float& f) {
    float x  = v * 256.0f;
    float fl = floorf(x);
    i0 = (int)fl;
    f  = x - fl;
    i1 = (i0 + 1) & 255;
}

// ---------------------------------------------------------------------------
__global__ void __launch_bounds__(256) scatter_kernel(const float* __restrict__ V,
                                                      const float* __restrict__ N) {
    int p = blockIdx.x * 256 + threadIdx.x;
    if (p >= NPTS) return;
    float vx = V[3 * p + 0], vy = V[3 * p + 1], vz = V[3 * p + 2];
    float nx = N[3 * p + 0], ny = N[3 * p + 1], nz = N[3 * p + 2];

    int ix0, ix1, iy0, iy1, iz0, iz1;
    float fx, fy, fz;
    corner_setup(vx, ix0, ix1, fx);
    corner_setup(vy, iy0, iy1, fy);
    corner_setup(vz, iz0, iz1, fz);

    float wx[2] = {1.0f - fx, fx};
    float wy[2] = {1.0f - fy, fy};
    float wz[2] = {1.0f - fz, fz};
    int ix[2] = {ix0, ix1}, iy[2] = {iy0, iy1}, iz[2] = {iz0, iz1};

#pragma unroll
    for (int c = 0; c < 8; c++) {
        int b0 = (c >> 2) & 1, b1 = (c >> 1) & 1, b2 = c & 1;
        int lin = (((ix[b0] << 8) | iy[b1]) << 8) | iz[b2];
        float w = wx[b0] * wy[b1] * wz[b2];
        asm volatile("red.global.add.v2.f32 [%0], {%1, %2};"
                     :: "l"(&gA[lin]), "f"(w * nx), "f"(w * ny) : "memory");
        atomicAdd(&gZ[lin], w * nz);
    }
}

// ---------------------------------------------------------------------------
// Warp-level 256-pt FFT: 8 complex per thread.
// Input: reg j holds x[32*br3(j)+lane]. Output: lane holds X[j + 8*br5(lane)].
// ---------------------------------------------------------------------------
__device__ __forceinline__ void xstage(float (&ar)[8], float (&ai)[8], int lane, int h,
                                       float twr_in, float twi_in) {
    const bool up = (lane & h) != 0;
    const float s  = up ? -1.0f : 1.0f;
    const float tr = up ? twr_in : 1.0f;
    const float ti = up ? twi_in : 0.0f;
#pragma unroll
    for (int k = 0; k < 8; k++) {
        float orr = __shfl_xor_sync(0xffffffffu, ar[k], h);
        float ori = __shfl_xor_sync(0xffffffffu, ai[k], h);
        float dr = fmaf(s, ar[k], orr);
        float di = fmaf(s, ai[k], ori);
        ar[k] = dr * tr - di * ti;
        ai[k] = dr * ti + di * tr;
    }
}

template <int DIR>
__device__ __forceinline__ void warp_fft256_reg(float (&ar)[8], float (&ai)[8], int lane) {
    const float D = (float)DIR;
    const float C = 0.70710678118654752440f;
    float tr, ti;

#pragma unroll
    for (int p = 0; p < 8; p += 2) {
        tr = ar[p + 1]; ti = ai[p + 1];
        ar[p + 1] = ar[p] - tr;  ai[p + 1] = ai[p] - ti;
        ar[p] += tr;             ai[p] += ti;
    }
#pragma unroll
    for (int q = 0; q < 8; q += 4) {
        tr = ar[q + 2]; ti = ai[q + 2];
        ar[q + 2] = ar[q] - tr;  ai[q + 2] = ai[q] - ti;
        ar[q] += tr;             ai[q] += ti;
        tr = -D * ai[q + 3];     ti = D * ar[q + 3];
        ar[q + 3] = ar[q + 1] - tr;  ai[q + 3] = ai[q + 1] - ti;
        ar[q + 1] += tr;             ai[q + 1] += ti;
    }
    tr = ar[4]; ti = ai[4];
    ar[4] = ar[0] - tr; ai[4] = ai[0] - ti; ar[0] += tr; ai[0] += ti;
    tr = C * (ar[5] - D * ai[5]); ti = C * (ai[5] + D * ar[5]);
    ar[5] = ar[1] - tr; ai[5] = ai[1] - ti; ar[1] += tr; ai[1] += ti;
    tr = -D * ai[6]; ti = D * ar[6];
    ar[6] = ar[2] - tr; ai[6] = ai[2] - ti; ar[2] += tr; ai[2] += ti;
    tr = -C * (ar[7] + D * ai[7]); ti = C * (D * ar[7] - ai[7]);
    ar[7] = ar[3] - tr; ai[7] = ai[3] - ti; ar[3] += tr; ai[3] += ti;

    float w1r, w1i;
    __sincosf(D * 0.024543692606170259f * (float)lane, &w1i, &w1r);   // 2*pi/256
    float wr = w1r, wi = w1i;
#pragma unroll
    for (int k = 1; k < 8; k++) {
        tr = ar[k] * wr - ai[k] * wi;
        ai[k] = ar[k] * wi + ai[k] * wr;
        ar[k] = tr;
        if (k < 7) { float nr = wr * w1r - wi * w1i; wi = wr * w1i + wi * w1r; wr = nr; }
    }

    float s16r, s16i, s8r, s8i, s4r, s4i;
    __sincosf(D * 0.19634954084936207f * (float)(lane & 15), &s16i, &s16r);  // pi/16
    __sincosf(D * 0.39269908169872414f * (float)(lane & 7),  &s8i,  &s8r);   // pi/8
    __sincosf(D * 0.78539816339744831f * (float)(lane & 3),  &s4i,  &s4r);   // pi/4
    xstage(ar, ai, lane, 16, s16r, s16i);
    xstage(ar, ai, lane, 8,  s8r,  s8i);
    xstage(ar, ai, lane, 4,  s4r,  s4i);
    xstage(ar, ai, lane, 2, (lane & 1) ? 0.0f : 1.0f, (lane & 1) ? D : 0.0f);
    xstage(ar, ai, lane, 1, 1.0f, 0.0f);
}

// smem address map for a 256-entry line: addr(k) = 9*(k>>3) + (k&7)
__device__ __forceinline__ int lmap(int k) { return 9 * (k >> 3) + (k & 7); }

// ---------------------------------------------------------------------------
// A axis-2 pass + Hermitian channel split into compact gX, gY (k2 <= 135).
// ---------------------------------------------------------------------------
__global__ void __launch_bounds__(256) fft_axis2_split(const float2* __restrict__ A,
                                                       float2* __restrict__ X,
                                                       float2* __restrict__ Y) {
    __shared__ float s_re[8][288];
    __shared__ float s_im[8][288];
    int w = threadIdx.x >> 5, lane = threadIdx.x & 31;
    int line = blockIdx.x * 8 + w;
    int ibase = line * 256;
    int obase = line * NH;

    float ar[8], ai[8];
    const int br3[8] = {0, 4, 2, 6, 1, 5, 3, 7};
#pragma unroll
    for (int t = 0; t < 8; t++) {
        float2 v = A[ibase + 32 * br3[t] + lane];
        ar[t] = v.x; ai[t] = v.y;
    }
    warp_fft256_reg<-1>(ar, ai, lane);

    int m = (int)(__brev((unsigned)lane) >> 27);
#pragma unroll
    for (int t = 0; t < 8; t++) {
        s_re[w][9 * m + t] = ar[t];
        s_im[w][9 * m + t] = ai[t];
    }
    __syncwarp();

#pragma unroll
    for (int t = 0; t < 5; t++) {
        int k = lane + 32 * t;
        if (t < 4 || lane < 8) {
            int km = (256 - k) & 255;
            float ur = s_re[w][lmap(k)],  ui = s_im[w][lmap(k)];
            float vr = s_re[w][lmap(km)], vi = s_im[w][lmap(km)];
            X[obase + k] = make_float2(0.5f * (ur + vr),  0.5f * (ui - vi));
            Y[obase + k] = make_float2(0.5f * (ui + vi), -0.5f * (ur - vr));
        }
    }
}

// ---------------------------------------------------------------------------
// z-channel axis-2 forward R2C into compact gW.
// ---------------------------------------------------------------------------
__global__ void __launch_bounds__(256) fft_axis2_r2c(const float* __restrict__ in,
                                                     float2* __restrict__ g) {
    __shared__ float s_re[8][288];
    __shared__ float s_im[8][288];
    int w = threadIdx.x >> 5, lane = threadIdx.x & 31;
    int pj = blockIdx.x * 8 + w;
    int i0 = pj >> 7, j = pj & 127;
    int la = (i0 << 16) | (j << 9);
    int lb = la + 256;
    int oa = (i0 * 256 + 2 * j) * NH;
    int ob = oa + NH;

    float ar[8], ai[8];
    const int br3[8] = {0, 4, 2, 6, 1, 5, 3, 7};
#pragma unroll
    for (int t = 0; t < 8; t++) {
        int idx = 32 * br3[t] + lane;
        ar[t] = in[la + idx];
        ai[t] = in[lb + idx];
    }
    warp_fft256_reg<-1>(ar, ai, lane);

    int m = (int)(__brev((unsigned)lane) >> 27);
#pragma unroll
    for (int t = 0; t < 8; t++) {
        s_re[w][9 * m + t] = ar[t];
        s_im[w][9 * m + t] = ai[t];
    }
    __syncwarp();

#pragma unroll
    for (int t = 0; t < 5; t++) {
        int k = lane + 32 * t;
        if (t < 4 || lane < 8) {
            int km = (256 - k) & 255;
            float ur = s_re[w][lmap(k)],  ui = s_im[w][lmap(k)];
            float vr = s_re[w][lmap(km)], vi = s_im[w][lmap(km)];
            g[oa + k] = make_float2(0.5f * (ur + vr),  0.5f * (ui - vi));
            g[ob + k] = make_float2(0.5f * (ui + vi), -0.5f * (ur - vr));
        }
    }
}

// ---------------------------------------------------------------------------
// axis-2 inverse C2R: compact Hermitian lines -> real full-stride lines.
// ---------------------------------------------------------------------------
__global__ void __launch_bounds__(256) fft_axis2_c2r(const float2* __restrict__ g,
                                                     float* __restrict__ outr) {
    __shared__ float s_re[8][288];
    __shared__ float s_im[8][288];
    int w = threadIdx.x >> 5, lane = threadIdx.x & 31;
    int pj = blockIdx.x * 8 + w;
    int i0 = pj >> 7, j = pj & 127;
    int la = (i0 << 16) | (j << 9);
    int lb = la + 256;
    int oa = (i0 * 256 + 2 * j) * NH;
    int ob = oa + NH;

#pragma unroll
    for (int t = 0; t < 5; t++) {
        int k = lane + 32 * t;
        if (t < 4 || lane == 0) {             // k <= 128
            float2 Ha = g[oa + k];
            float2 Hb = g[ob + k];
            s_re[w][lmap(k)] = Ha.x - Hb.y;
            s_im[w][lmap(k)] = Ha.y + Hb.x;
            if (k >= 1 && k <= 127) {
                s_re[w][lmap(256 - k)] = Ha.x + Hb.y;
                s_im[w][lmap(256 - k)] = Hb.x - Ha.y;
            }
        }
    }
    __syncwarp();

    float ar[8], ai[8];
    const int br3[8] = {0, 4, 2, 6, 1, 5, 3, 7};
#pragma unroll
    for (int t = 0; t < 8; t++) {
        int idx = 32 * br3[t] + lane;
        ar[t] = s_re[w][lmap(idx)];
        ai[t] = s_im[w][lmap(idx)];
    }
    warp_fft256_reg<1>(ar, ai, lane);

    int obp = 8 * (int)(__brev((unsigned)lane) >> 27);
    float4* pa = (float4*)(outr + la + obp);
    float4* pb = (float4*)(outr + lb + obp);
    pa[0] = make_float4(ar[0], ar[1], ar[2], ar[3]);
    pa[1] = make_float4(ar[4], ar[5], ar[6], ar[7]);
    pb[0] = make_float4(ai[0], ai[1], ai[2], ai[3]);
    pb[1] = make_float4(ai[4], ai[5], ai[6], ai[7]);
}

// ---------------------------------------------------------------------------
// Strided-axis pass (compact volumes). blockIdx.y = outer, blockIdx.x = chunk.
// ---------------------------------------------------------------------------
template <int DIR>
__global__ void __launch_bounds__(256) fft_strided_reg(float2* __restrict__ g,
                                                       int S, int outerStride) {
    __shared__ float s_re[2304];
    __shared__ float s_im[2304];

    int tid  = threadIdx.x;
    int base = blockIdx.y * outerStride + blockIdx.x * 8;

#pragma unroll
    for (int it = 0; it < 8; it++) {
        int e = it * 256 + tid;
        int r = e >> 3, c = e & 7;
        float2 v = g[base + r * S + c];
        int a = 9 * r + (c ^ ((r >> 5) & 7));
        s_re[a] = v.x; s_im[a] = v.y;
    }
    __syncthreads();

    int w = tid >> 5, lane = tid & 31;
    float ar[8], ai[8];
    const int br3[8] = {0, 4, 2, 6, 1, 5, 3, 7};
#pragma unroll
    for (int j = 0; j < 8; j++) {
        int r = 32 * br3[j] + lane;
        int a = 9 * r + (w ^ ((r >> 5) & 7));
        ar[j] = s_re[a]; ai[j] = s_im[a];
    }

    warp_fft256_reg<DIR>(ar, ai, lane);
    __syncthreads();

    int k2 = (int)(__brev((unsigned)lane) >> 27);
#pragma unroll
    for (int k1 = 0; k1 < 8; k1++) {
        int r = k1 + 8 * k2;
        int a = 9 * r + (w ^ ((r >> 5) & 7));
        s_re[a] = ar[k1]; s_im[a] = ai[k1];
    }
    __syncthreads();

#pragma unroll
    for (int it = 0; it < 8; it++) {
        int e = it * 256 + tid;
        int r = e >> 3, c = e & 7;
        int a = 9 * r + (c ^ ((r >> 5) & 7));
        float2 v;
        v.x = s_re[a]; v.y = s_im[a];
        g[base + r * S + c] = v;
    }
}

// Dual-volume variant: identical body, blockIdx.z selects gX or gY (axis-1).
__global__ void __launch_bounds__(256) fft_strided_xy(float2* __restrict__ X,
                                                      float2* __restrict__ Y,
                                                      int S, int outerStride) {
    __shared__ float s_re[2304];
    __shared__ float s_im[2304];
    float2* g = (blockIdx.z == 0) ? X : Y;

    int tid  = threadIdx.x;
    int base = blockIdx.y * outerStride + blockIdx.x * 8;

#pragma unroll
    for (int it = 0; it < 8; it++) {
        int e = it * 256 + tid;
        int r = e >> 3, c = e & 7;
        float2 v = g[base + r * S + c];
        int a = 9 * r + (c ^ ((r >> 5) & 7));
        s_re[a] = v.x; s_im[a] = v.y;
    }
    __syncthreads();

    int w = tid >> 5, lane = tid & 31;
    float ar[8], ai[8];
    const int br3[8] = {0, 4, 2, 6, 1, 5, 3, 7};
#pragma unroll
    for (int j = 0; j < 8; j++) {
        int r = 32 * br3[j] + lane;
        int a = 9 * r + (w ^ ((r >> 5) & 7));
        ar[j] = s_re[a]; ai[j] = s_im[a];
    }

    warp_fft256_reg<-1>(ar, ai, lane);
    __syncthreads();

    int k2 = (int)(__brev((unsigned)lane) >> 27);
#pragma unroll
    for (int k1 = 0; k1 < 8; k1++) {
        int r = k1 + 8 * k2;
        int a = 9 * r + (w ^ ((r >> 5) & 7));
        s_re[a] = ar[k1]; s_im[a] = ai[k1];
    }
    __syncthreads();

#pragma unroll
    for (int it = 0; it < 8; it++) {
        int e = it * 256 + tid;
        int r = e >> 3, c = e & 7;
        int a = 9 * r + (c ^ ((r >> 5) & 7));
        float2 v;
        v.x = s_re[a]; v.y = s_im[a];
        g[base + r * S + c] = v;
    }
}

// ---------------------------------------------------------------------------
// FUSED (R9 champion structure): forward axis-0 FFT of X^ and Y^ tiles +
// spectral combine (gW streamed) + inverse axis-0 FFT of Phi -> gW.
// blockIdx.y = k1, blockIdx.x = k2 chunk t2.
// ---------------------------------------------------------------------------
__global__ void __launch_bounds__(256) fused_axis0_combine() {
    __shared__ float sX_re[2304], sX_im[2304];
    __shared__ float sY_re[2304], sY_im[2304];

    int tid  = threadIdx.x;
    int k1   = blockIdx.y;
    int t2   = blockIdx.x;
    int cbase = k1 * NH + t2 * 8;

#pragma unroll
    for (int it = 0; it < 8; it++) {
        int e = it * 256 + tid;
        int r = e >> 3, c = e & 7;
        int a = 9 * r + (c ^ ((r >> 5) & 7));
        int gi = r * (256 * NH) + cbase + c;
        float2 vx = gX[gi];
        sX_re[a] = vx.x; sX_im[a] = vx.y;
        float2 vy = gY[gi];
        sY_re[a] = vy.x; sY_im[a] = vy.y;
    }
    __syncthreads();

    int w = tid >> 5, lane = tid & 31;
    const int br3[8] = {0, 4, 2, 6, 1, 5, 3, 7};
    int k2r = (int)(__brev((unsigned)lane) >> 27);
    float ar[8], ai[8];

#pragma unroll
    for (int j = 0; j < 8; j++) {
        int r = 32 * br3[j] + lane;
        int a = 9 * r + (w ^ ((r >> 5) & 7));
        ar[j] = sX_re[a]; ai[j] = sX_im[a];
    }
    warp_fft256_reg<-1>(ar, ai, lane);
#pragma unroll
    for (int k = 0; k < 8; k++) {
        int r = k + 8 * k2r;
        int a = 9 * r + (w ^ ((r >> 5) & 7));
        sX_re[a] = ar[k]; sX_im[a] = ai[k];
    }
    __syncwarp();

#pragma unroll
    for (int j = 0; j < 8; j++) {
        int r = 32 * br3[j] + lane;
        int a = 9 * r + (w ^ ((r >> 5) & 7));
        ar[j] = sY_re[a]; ai[j] = sY_im[a];
    }
    warp_fft256_reg<-1>(ar, ai, lane);
#pragma unroll
    for (int k = 0; k < 8; k++) {
        int r = k + 8 * k2r;
        int a = 9 * r + (w ^ ((r >> 5) & 7));
        sY_re[a] = ar[k]; sY_im[a] = ai[k];
    }
    __syncthreads();

    float w1 = (float)(k1 - ((k1 >= 128) ? 256 : 0));
#pragma unroll
    for (int it = 0; it < 8; it++) {
        int e = it * 256 + tid;
        int r = e >> 3, c = e & 7;
        int a = 9 * r + (c ^ ((r >> 5) & 7));

        float Nxr = sX_re[a], Nxi = sX_im[a];
        float Nyr = sY_re[a], Nyi = sY_im[a];
        float2 Bz = gW[r * (256 * NH) + cbase + c];

        int k0 = r, k2 = 8 * t2 + c;
        float w0 = (float)(k0 - ((k0 >= 128) ? 256 : 0));
        float w2 = (float)(k2 - ((k2 >= 128) ? 256 : 0));

        float Dr = Nxr * w0 + Nyr * w1 + Bz.x * w2;
        float Di = Nxi * w0 + Nyi * w1 + Bz.y * w2;

        float s = w0 * w0 + w1 * w1 + w2 * w2;
        float G = expf(s * (-200.0f / 65536.0f));
        float denom = -39.478417604357434f * s + 1e-6f;
        float f = (6.283185307179586f * G / denom) * (1.0f / 16777216.0f);

        float pr = Di * f;
        float pi = -Dr * f;
        if ((r | k1 | t2 | c) == 0) { pr = 0.0f; pi = 0.0f; }

        sX_re[a] = pr; sX_im[a] = pi;
    }
    __syncthreads();

#pragma unroll
    for (int j = 0; j < 8; j++) {
        int r = 32 * br3[j] + lane;
        int a = 9 * r + (w ^ ((r >> 5) & 7));
        ar[j] = sX_re[a]; ai[j] = sX_im[a];
    }
    warp_fft256_reg<1>(ar, ai, lane);
    __syncthreads();
#pragma unroll
    for (int j = 0; j < 8; j++) {
        int r = j + 8 * k2r;
        int a = 9 * r + (w ^ ((r >> 5) & 7));
        sX_re[a] = ar[j]; sX_im[a] = ai[j];
    }
    __syncthreads();

#pragma unroll
    for (int it = 0; it < 8; it++) {
        int e = it * 256 + tid;
        int r = e >> 3, c = e & 7;
        int a = 9 * r + (c ^ ((r >> 5) & 7));
        float2 v;
        v.x = sX_re[a]; v.y = sX_im[a];
        gW[r * (256 * NH) + cbase + c] = v;
    }
}

// ---------------------------------------------------------------------------
__global__ void __launch_bounds__(256) interp_kernel(const float* __restrict__ V) {
    int p = blockIdx.x * 256 + threadIdx.x;
    float val = 0.0f;
    if (p < NPTS) {
        float vx = V[3 * p + 0], vy = V[3 * p + 1], vz = V[3 * p + 2];
        int ix0, ix1, iy0, iy1, iz0, iz1;
        float fx, fy, fz;
        corner_setup(vx, ix0, ix1, fx);
        corner_setup(vy, iy0, iy1, fy);
        corner_setup(vz, iz0, iz1, fz);
        float wx[2] = {1.0f - fx, fx};
        float wy[2] = {1.0f - fy, fy};
        float wz[2] = {1.0f - fz, fz};
        int ix[2] = {ix0, ix1}, iy[2] = {iy0, iy1}, iz[2] = {iz0, iz1};
#pragma unroll
        for (int c = 0; c < 8; c++) {
            int b0 = (c >> 2) & 1, b1 = (c >> 1) & 1, b2 = c & 1;
            int lin = (((ix[b0] << 8) | iy[b1]) << 8) | iz[b2];
            val += wx[b0] * wy[b1] * wz[b2] * __ldg(&gZ[lin]);
        }
    }
    __shared__ float red[256];
    red[threadIdx.x] = val;
    __syncthreads();
#pragma unroll
    for (int off = 128; off > 0; off >>= 1) {
        if (threadIdx.x < off) red[threadIdx.x] += red[threadIdx.x + off];
        __syncthreads();
    }
    if (threadIdx.x == 0) atomicAdd(&g_accum, (double)red[0]);
}

// ---------------------------------------------------------------------------
__global__ void __launch_bounds__(256) final_kernel(float4* __restrict__ out) {
    int idx = blockIdx.x * 256 + threadIdx.x;
    float mean = (float)(g_accum * (1.0 / (double)NPTS));
    float f0 = gZ[0] - mean;
    float sc = -0.5f / fabsf(f0);
    float4 v = *((const float4*)gZ + idx);
    v.x = (v.x - mean) * sc;
    v.y = (v.y - mean) * sc;
    v.z = (v.z - mean) * sc;
    v.w = (v.w - mean) * sc;
    out[idx] = v;
}

// ---------------------------------------------------------------------------
extern "C" void kernel_launch(void* const* d_in, const int* in_sizes, int n_in,
                              void* d_out, int out_size) {
    const float* V  = (const float*)d_in[0];
    const float* Np = (const float*)d_in[1];

    void *pA, *pX, *pY, *pW, *pZ, *pAcc;
    cudaGetSymbolAddress(&pA, gA);
    cudaGetSymbolAddress(&pX, gX);
    cudaGetSymbolAddress(&pY, gY);
    cudaGetSymbolAddress(&pW, gW);
    cudaGetSymbolAddress(&pZ, gZ);
    cudaGetSymbolAddress(&pAcc, g_accum);

    cudaMemsetAsync(pA, 0, (size_t)NVOX * sizeof(float2));
    cudaMemsetAsync(pZ, 0, (size_t)NVOX * sizeof(float));
    cudaMemsetAsync(pAcc, 0, sizeof(double));

    const int PB = (NPTS + 255) / 256;

    scatter_kernel<<<PB, 256>>>(V, Np);

    dim3 gHalf(17, 256);
    dim3 gHalf2(17, 256, 2);
    const int S1 = NH;
    const int O1 = 256 * NH;
    const int S0 = 256 * NH;
    const int O0 = NH;

    // x,y channels: axis-2 FFT + Hermitian split into compact gX, gY
    fft_axis2_split<<<8192, 256>>>((const float2*)pA, (float2*)pX, (float2*)pY);
    fft_strided_xy<<<gHalf2, 256>>>((float2*)pX, (float2*)pY, S1, O1);  // X,Y axis 1

    // z channel: R2C axis 2 -> compact gW, then axes 1, 0
    fft_axis2_r2c<<<4096, 256>>>((const float*)pZ, (float2*)pW);
    fft_strided_reg<-1><<<gHalf, 256>>>((float2*)pW, S1, O1);   // W axis 1
    fft_strided_reg<-1><<<gHalf, 256>>>((float2*)pW, S0, O0);   // W axis 0

    // fused: fwd axis-0 of X,Y + combine (gW streamed) + inverse axis-0 of Phi
    fused_axis0_combine<<<gHalf, 256>>>();

    // inverse axis 1, then C2R axis 2 into gZ
    fft_strided_reg<1><<<gHalf, 256>>>((float2*)pW, S1, O1);
    fft_axis2_c2r<<<4096, 256>>>((const float2*)pW, (float*)pZ);

    interp_kernel<<<PB, 256>>>(V);
    final_kernel<<<16384, 256>>>((float4*)d_out);
}

// round 15
// speedup vs baseline: 1.3850x; 1.0066x over previous
#include <cuda_runtime.h>
#include <math.h>

static constexpr int NPTS = 500000;
static constexpr int NVOX = 1 << 24;       // 256^3
static constexpr int NH   = 136;           // compact k2 width (17 chunks of 8)
static constexpr int NHVOX = 256 * 256 * NH;

__device__ float2 gA[NVOX];    // scatter target: ras_x + i*ras_y
__device__ float2 gX[NHVOX];   // N^x spectrum (axes 2 then 1), compact k2<=135
__device__ float2 gY[NHVOX];   // N^y spectrum, compact
__device__ float2 gW[NHVOX];   // N^z spectrum (axes 2,1) -> Phi -> partial inverse
__device__ float  gZ[NVOX];    // ras_z (real) in; phi (real) out
__device__ double g_accum;

// ---------------------------------------------------------------------------
__device__ __forceinline__ void corner_setup(float v, int& i0, int& i1, float& f) {
    float x  = v * 256.0f;
    float fl = floorf(x);
    i0 = (int)fl;
    f  = x - fl;
    i1 = (i0 + 1) & 255;
}

// ---------------------------------------------------------------------------
__global__ void __launch_bounds__(256) scatter_kernel(const float* __restrict__ V,
                                                      const float* __restrict__ N) {
    int p = blockIdx.x * 256 + threadIdx.x;
    if (p >= NPTS) return;
    float vx = V[3 * p + 0], vy = V[3 * p + 1], vz = V[3 * p + 2];
    float nx = N[3 * p + 0], ny = N[3 * p + 1], nz = N[3 * p + 2];

    int ix0, ix1, iy0, iy1, iz0, iz1;
    float fx, fy, fz;
    corner_setup(vx, ix0, ix1, fx);
    corner_setup(vy, iy0, iy1, fy);
    corner_setup(vz, iz0, iz1, fz);

    float wx[2] = {1.0f - fx, fx};
    float wy[2] = {1.0f - fy, fy};
    float wz[2] = {1.0f - fz, fz};
    int ix[2] = {ix0, ix1}, iy[2] = {iy0, iy1}, iz[2] = {iz0, iz1};

#pragma unroll
    for (int c = 0; c < 8; c++) {
        int b0 = (c >> 2) & 1, b1 = (c >> 1) & 1, b2 = c & 1;
        int lin = (((ix[b0] << 8) | iy[b1]) << 8) | iz[b2];
        float w = wx[b0] * wy[b1] * wz[b2];
        asm volatile("red.global.add.v2.f32 [%0], {%1, %2};"
                     :: "l"(&gA[lin]), "f"(w * nx), "f"(w * ny) : "memory");
        atomicAdd(&gZ[lin], w * nz);
    }
}

// ---------------------------------------------------------------------------
// Warp-level 256-pt FFT: 8 complex per thread.
// Input: reg j holds x[32*br3(j)+lane]. Output: lane holds X[j + 8*br5(lane)].
// ---------------------------------------------------------------------------
__device__ __forceinline__ void xstage(float (&ar)[8], float (&ai)[8], int lane, int h,
                                       float twr_in, float twi_in) {
    const bool up = (lane & h) != 0;
    const float s  = up ? -1.0f : 1.0f;
    const float tr = up ? twr_in : 1.0f;
    const float ti = up ? twi_in : 0.0f;
#pragma unroll
    for (int k = 0; k < 8; k++) {
        float orr = __shfl_xor_sync(0xffffffffu, ar[k], h);
        float ori = __shfl_xor_sync(0xffffffffu, ai[k], h);
        float dr = fmaf(s, ar[k], orr);
        float di = fmaf(s, ai[k], ori);
        ar[k] = dr * tr - di * ti;
        ai[k] = dr * ti + di * tr;
    }
}

template <int DIR>
__device__ __forceinline__ void warp_fft256_reg(float (&ar)[8], float (&ai)[8], int lane) {
    const float D = (float)DIR;
    const float C = 0.70710678118654752440f;
    float tr, ti;

#pragma unroll
    for (int p = 0; p < 8; p += 2) {
        tr = ar[p + 1]; ti = ai[p + 1];
        ar[p + 1] = ar[p] - tr;  ai[p + 1] = ai[p] - ti;
        ar[p] += tr;             ai[p] += ti;
    }
#pragma unroll
    for (int q = 0; q < 8; q += 4) {
        tr = ar[q + 2]; ti = ai[q + 2];
        ar[q + 2] = ar[q] - tr;  ai[q + 2] = ai[q] - ti;
        ar[q] += tr;             ai[q] += ti;
        tr = -D * ai[q + 3];     ti = D * ar[q + 3];
        ar[q + 3] = ar[q + 1] - tr;  ai[q + 3] = ai[q + 1] - ti;
        ar[q + 1] += tr;             ai[q + 1] += ti;
    }
    tr = ar[4]; ti = ai[4];
    ar[4] = ar[0] - tr; ai[4] = ai[0] - ti; ar[0] += tr; ai[0] += ti;
    tr = C * (ar[5] - D * ai[5]); ti = C * (ai[5] + D * ar[5]);
    ar[5] = ar[1] - tr; ai[5] = ai[1] - ti; ar[1] += tr; ai[1] += ti;
    tr = -D * ai[6]; ti = D * ar[6];
    ar[6] = ar[2] - tr; ai[6] = ai[2] - ti; ar[2] += tr; ai[2] += ti;
    tr = -C * (ar[7] + D * ai[7]); ti = C * (D * ar[7] - ai[7]);
    ar[7] = ar[3] - tr; ai[7] = ai[3] - ti; ar[3] += tr; ai[3] += ti;

    float w1r, w1i;
    __sincosf(D * 0.024543692606170259f * (float)lane, &w1i, &w1r);   // 2*pi/256
    float wr = w1r, wi = w1i;
#pragma unroll
    for (int k = 1; k < 8; k++) {
        tr = ar[k] * wr - ai[k] * wi;
        ai[k] = ar[k] * wi + ai[k] * wr;
        ar[k] = tr;
        if (k < 7) { float nr = wr * w1r - wi * w1i; wi = wr * w1i + wi * w1r; wr = nr; }
    }

    float s16r, s16i, s8r, s8i, s4r, s4i;
    __sincosf(D * 0.19634954084936207f * (float)(lane & 15), &s16i, &s16r);  // pi/16
    __sincosf(D * 0.39269908169872414f * (float)(lane & 7),  &s8i,  &s8r);   // pi/8
    __sincosf(D * 0.78539816339744831f * (float)(lane & 3),  &s4i,  &s4r);   // pi/4
    xstage(ar, ai, lane, 16, s16r, s16i);
    xstage(ar, ai, lane, 8,  s8r,  s8i);
    xstage(ar, ai, lane, 4,  s4r,  s4i);
    xstage(ar, ai, lane, 2, (lane & 1) ? 0.0f : 1.0f, (lane & 1) ? D : 0.0f);
    xstage(ar, ai, lane, 1, 1.0f, 0.0f);
}

// smem address map for a 256-entry line: addr(k) = 9*(k>>3) + (k&7)
__device__ __forceinline__ int lmap(int k) { return 9 * (k >> 3) + (k & 7); }

// ---------------------------------------------------------------------------
// A axis-2 pass + Hermitian channel split into compact gX, gY (k2 <= 135).
// ---------------------------------------------------------------------------
__global__ void __launch_bounds__(256) fft_axis2_split(const float2* __restrict__ A,
                                                       float2* __restrict__ X,
                                                       float2* __restrict__ Y) {
    __shared__ float s_re[8][288];
    __shared__ float s_im[8][288];
    int w = threadIdx.x >> 5, lane = threadIdx.x & 31;
    int line = blockIdx.x * 8 + w;
    int ibase = line * 256;
    int obase = line * NH;

    float ar[8], ai[8];
    const int br3[8] = {0, 4, 2, 6, 1, 5, 3, 7};
#pragma unroll
    for (int t = 0; t < 8; t++) {
        float2 v = A[ibase + 32 * br3[t] + lane];
        ar[t] = v.x; ai[t] = v.y;
    }
    warp_fft256_reg<-1>(ar, ai, lane);

    int m = (int)(__brev((unsigned)lane) >> 27);
#pragma unroll
    for (int t = 0; t < 8; t++) {
        s_re[w][9 * m + t] = ar[t];
        s_im[w][9 * m + t] = ai[t];
    }
    __syncwarp();

#pragma unroll
    for (int t = 0; t < 5; t++) {
        int k = lane + 32 * t;
        if (t < 4 || lane < 8) {
            int km = (256 - k) & 255;
            float ur = s_re[w][lmap(k)],  ui = s_im[w][lmap(k)];
            float vr = s_re[w][lmap(km)], vi = s_im[w][lmap(km)];
            X[obase + k] = make_float2(0.5f * (ur + vr),  0.5f * (ui - vi));
            Y[obase + k] = make_float2(0.5f * (ui + vi), -0.5f * (ur - vr));
        }
    }
}

// ---------------------------------------------------------------------------
// z-channel axis-2 forward R2C into compact gW.
// ---------------------------------------------------------------------------
__global__ void __launch_bounds__(256) fft_axis2_r2c(const float* __restrict__ in,
                                                     float2* __restrict__ g) {
    __shared__ float s_re[8][288];
    __shared__ float s_im[8][288];
    int w = threadIdx.x >> 5, lane = threadIdx.x & 31;
    int pj = blockIdx.x * 8 + w;
    int i0 = pj >> 7, j = pj & 127;
    int la = (i0 << 16) | (j << 9);
    int lb = la + 256;
    int oa = (i0 * 256 + 2 * j) * NH;
    int ob = oa + NH;

    float ar[8], ai[8];
    const int br3[8] = {0, 4, 2, 6, 1, 5, 3, 7};
#pragma unroll
    for (int t = 0; t < 8; t++) {
        int idx = 32 * br3[t] + lane;
        ar[t] = in[la + idx];
        ai[t] = in[lb + idx];
    }
    warp_fft256_reg<-1>(ar, ai, lane);

    int m = (int)(__brev((unsigned)lane) >> 27);
#pragma unroll
    for (int t = 0; t < 8; t++) {
        s_re[w][9 * m + t] = ar[t];
        s_im[w][9 * m + t] = ai[t];
    }
    __syncwarp();

#pragma unroll
    for (int t = 0; t < 5; t++) {
        int k = lane + 32 * t;
        if (t < 4 || lane < 8) {
            int km = (256 - k) & 255;
            float ur = s_re[w][lmap(k)],  ui = s_im[w][lmap(k)];
            float vr = s_re[w][lmap(km)], vi = s_im[w][lmap(km)];
            g[oa + k] = make_float2(0.5f * (ur + vr),  0.5f * (ui - vi));
            g[ob + k] = make_float2(0.5f * (ui + vi), -0.5f * (ur - vr));
        }
    }
}

// ---------------------------------------------------------------------------
// axis-2 inverse C2R: compact Hermitian lines -> real full-stride lines.
// ---------------------------------------------------------------------------
__global__ void __launch_bounds__(256) fft_axis2_c2r(const float2* __restrict__ g,
                                                     float* __restrict__ outr) {
    __shared__ float s_re[8][288];
    __shared__ float s_im[8][288];
    int w = threadIdx.x >> 5, lane = threadIdx.x & 31;
    int pj = blockIdx.x * 8 + w;
    int i0 = pj >> 7, j = pj & 127;
    int la = (i0 << 16) | (j << 9);
    int lb = la + 256;
    int oa = (i0 * 256 + 2 * j) * NH;
    int ob = oa + NH;

#pragma unroll
    for (int t = 0; t < 5; t++) {
        int k = lane + 32 * t;
        if (t < 4 || lane == 0) {             // k <= 128
            float2 Ha = g[oa + k];
            float2 Hb = g[ob + k];
            s_re[w][lmap(k)] = Ha.x - Hb.y;
            s_im[w][lmap(k)] = Ha.y + Hb.x;
            if (k >= 1 && k <= 127) {
                s_re[w][lmap(256 - k)] = Ha.x + Hb.y;
                s_im[w][lmap(256 - k)] = Hb.x - Ha.y;
            }
        }
    }
    __syncwarp();

    float ar[8], ai[8];
    const int br3[8] = {0, 4, 2, 6, 1, 5, 3, 7};
#pragma unroll
    for (int t = 0; t < 8; t++) {
        int idx = 32 * br3[t] + lane;
        ar[t] = s_re[w][lmap(idx)];
        ai[t] = s_im[w][lmap(idx)];
    }
    warp_fft256_reg<1>(ar, ai, lane);

    int obp = 8 * (int)(__brev((unsigned)lane) >> 27);
    float4* pa = (float4*)(outr + la + obp);
    float4* pb = (float4*)(outr + lb + obp);
    pa[0] = make_float4(ar[0], ar[1], ar[2], ar[3]);
    pa[1] = make_float4(ar[4], ar[5], ar[6], ar[7]);
    pb[0] = make_float4(ai[0], ai[1], ai[2], ai[3]);
    pb[1] = make_float4(ai[4], ai[5], ai[6], ai[7]);
}

// ---------------------------------------------------------------------------
// Strided-axis pass (compact volumes). blockIdx.y = outer, blockIdx.x = chunk.
// minBlocks=5 targets 51 regs -> 5 blocks/SM (occ 58%) to hide smem/shfl lat.
// ---------------------------------------------------------------------------
template <int DIR>
__global__ void __launch_bounds__(256, 5) fft_strided_reg(float2* __restrict__ g,
                                                          int S, int outerStride) {
    __shared__ float s_re[2304];
    __shared__ float s_im[2304];

    int tid  = threadIdx.x;
    int base = blockIdx.y * outerStride + blockIdx.x * 8;

#pragma unroll
    for (int it = 0; it < 8; it++) {
        int e = it * 256 + tid;
        int r = e >> 3, c = e & 7;
        float2 v = g[base + r * S + c];
        int a = 9 * r + (c ^ ((r >> 5) & 7));
        s_re[a] = v.x; s_im[a] = v.y;
    }
    __syncthreads();

    int w = tid >> 5, lane = tid & 31;
    float ar[8], ai[8];
    const int br3[8] = {0, 4, 2, 6, 1, 5, 3, 7};
#pragma unroll
    for (int j = 0; j < 8; j++) {
        int r = 32 * br3[j] + lane;
        int a = 9 * r + (w ^ ((r >> 5) & 7));
        ar[j] = s_re[a]; ai[j] = s_im[a];
    }

    warp_fft256_reg<DIR>(ar, ai, lane);
    __syncthreads();

    int k2 = (int)(__brev((unsigned)lane) >> 27);
#pragma unroll
    for (int k1 = 0; k1 < 8; k1++) {
        int r = k1 + 8 * k2;
        int a = 9 * r + (w ^ ((r >> 5) & 7));
        s_re[a] = ar[k1]; s_im[a] = ai[k1];
    }
    __syncthreads();

#pragma unroll
    for (int it = 0; it < 8; it++) {
        int e = it * 256 + tid;
        int r = e >> 3, c = e & 7;
        int a = 9 * r + (c ^ ((r >> 5) & 7));
        float2 v;
        v.x = s_re[a]; v.y = s_im[a];
        g[base + r * S + c] = v;
    }
}

// Dual-volume variant: identical body, blockIdx.z selects gX or gY (axis-1).
__global__ void __launch_bounds__(256, 5) fft_strided_xy(float2* __restrict__ X,
                                                         float2* __restrict__ Y,
                                                         int S, int outerStride) {
    __shared__ float s_re[2304];
    __shared__ float s_im[2304];
    float2* g = (blockIdx.z == 0) ? X : Y;

    int tid  = threadIdx.x;
    int base = blockIdx.y * outerStride + blockIdx.x * 8;

#pragma unroll
    for (int it = 0; it < 8; it++) {
        int e = it * 256 + tid;
        int r = e >> 3, c = e & 7;
        float2 v = g[base + r * S + c];
        int a = 9 * r + (c ^ ((r >> 5) & 7));
        s_re[a] = v.x; s_im[a] = v.y;
    }
    __syncthreads();

    int w = tid >> 5, lane = tid & 31;
    float ar[8], ai[8];
    const int br3[8] = {0, 4, 2, 6, 1, 5, 3, 7};
#pragma unroll
    for (int j = 0; j < 8; j++) {
        int r = 32 * br3[j] + lane;
        int a = 9 * r + (w ^ ((r >> 5) & 7));
        ar[j] = s_re[a]; ai[j] = s_im[a];
    }

    warp_fft256_reg<-1>(ar, ai, lane);
    __syncthreads();

    int k2 = (int)(__brev((unsigned)lane) >> 27);
#pragma unroll
    for (int k1 = 0; k1 < 8; k1++) {
        int r = k1 + 8 * k2;
        int a = 9 * r + (w ^ ((r >> 5) & 7));
        s_re[a] = ar[k1]; s_im[a] = ai[k1];
    }
    __syncthreads();

#pragma unroll
    for (int it = 0; it < 8; it++) {
        int e = it * 256 + tid;
        int r = e >> 3, c = e & 7;
        int a = 9 * r + (c ^ ((r >> 5) & 7));
        float2 v;
        v.x = s_re[a]; v.y = s_im[a];
        g[base + r * S + c] = v;
    }
}

// ---------------------------------------------------------------------------
// FUSED (champion structure): forward axis-0 FFT of X^ and Y^ tiles +
// spectral combine (gW streamed) + inverse axis-0 FFT of Phi -> gW.
// blockIdx.y = k1, blockIdx.x = k2 chunk t2.
// ---------------------------------------------------------------------------
__global__ void __launch_bounds__(256) fused_axis0_combine() {
    __shared__ float sX_re[2304], sX_im[2304];
    __shared__ float sY_re[2304], sY_im[2304];

    int tid  = threadIdx.x;
    int k1   = blockIdx.y;
    int t2   = blockIdx.x;
    int cbase = k1 * NH + t2 * 8;

#pragma unroll
    for (int it = 0; it < 8; it++) {
        int e = it * 256 + tid;
        int r = e >> 3, c = e & 7;
        int a = 9 * r + (c ^ ((r >> 5) & 7));
        int gi = r * (256 * NH) + cbase + c;
        float2 vx = gX[gi];
        sX_re[a] = vx.x; sX_im[a] = vx.y;
        float2 vy = gY[gi];
        sY_re[a] = vy.x; sY_im[a] = vy.y;
    }
    __syncthreads();

    int w = tid >> 5, lane = tid & 31;
    const int br3[8] = {0, 4, 2, 6, 1, 5, 3, 7};
    int k2r = (int)(__brev((unsigned)lane) >> 27);
    float ar[8], ai[8];

#pragma unroll
    for (int j = 0; j < 8; j++) {
        int r = 32 * br3[j] + lane;
        int a = 9 * r + (w ^ ((r >> 5) & 7));
        ar[j] = sX_re[a]; ai[j] = sX_im[a];
    }
    warp_fft256_reg<-1>(ar, ai, lane);
#pragma unroll
    for (int k = 0; k < 8; k++) {
        int r = k + 8 * k2r;
        int a = 9 * r + (w ^ ((r >> 5) & 7));
        sX_re[a] = ar[k]; sX_im[a] = ai[k];
    }
    __syncwarp();

#pragma unroll
    for (int j = 0; j < 8; j++) {
        int r = 32 * br3[j] + lane;
        int a = 9 * r + (w ^ ((r >> 5) & 7));
        ar[j] = sY_re[a]; ai[j] = sY_im[a];
    }
    warp_fft256_reg<-1>(ar, ai, lane);
#pragma unroll
    for (int k = 0; k < 8; k++) {
        int r = k + 8 * k2r;
        int a = 9 * r + (w ^ ((r >> 5) & 7));
        sY_re[a] = ar[k]; sY_im[a] = ai[k];
    }
    __syncthreads();

    float w1 = (float)(k1 - ((k1 >= 128) ? 256 : 0));
#pragma unroll
    for (int it = 0; it < 8; it++) {
        int e = it * 256 + tid;
        int r = e >> 3, c = e & 7;
        int a = 9 * r + (c ^ ((r >> 5) & 7));

        float Nxr = sX_re[a], Nxi = sX_im[a];
        float Nyr = sY_re[a], Nyi = sY_im[a];
        float2 Bz = gW[r * (256 * NH) + cbase + c];

        int k0 = r, k2 = 8 * t2 + c;
        float w0 = (float)(k0 - ((k0 >= 128) ? 256 : 0));
        float w2 = (float)(k2 - ((k2 >= 128) ? 256 : 0));

        float Dr = Nxr * w0 + Nyr * w1 + Bz.x * w2;
        float Di = Nxi * w0 + Nyi * w1 + Bz.y * w2;

        float s = w0 * w0 + w1 * w1 + w2 * w2;
        float G = expf(s * (-200.0f / 65536.0f));
        float denom = -39.478417604357434f * s + 1e-6f;
        float f = (6.283185307179586f * G / denom) * (1.0f / 16777216.0f);

        float pr = Di * f;
        float pi = -Dr * f;
        if ((r | k1 | t2 | c) == 0) { pr = 0.0f; pi = 0.0f; }

        sX_re[a] = pr; sX_im[a] = pi;
    }
    __syncthreads();

#pragma unroll
    for (int j = 0; j < 8; j++) {
        int r = 32 * br3[j] + lane;
        int a = 9 * r + (w ^ ((r >> 5) & 7));
        ar[j] = sX_re[a]; ai[j] = sX_im[a];
    }
    warp_fft256_reg<1>(ar, ai, lane);
    __syncthreads();
#pragma unroll
    for (int j = 0; j < 8; j++) {
        int r = j + 8 * k2r;
        int a = 9 * r + (w ^ ((r >> 5) & 7));
        sX_re[a] = ar[j]; sX_im[a] = ai[j];
    }
    __syncthreads();

#pragma unroll
    for (int it = 0; it < 8; it++) {
        int e = it * 256 + tid;
        int r = e >> 3, c = e & 7;
        int a = 9 * r + (c ^ ((r >> 5) & 7));
        float2 v;
        v.x = sX_re[a]; v.y = sX_im[a];
        gW[r * (256 * NH) + cbase + c] = v;
    }
}

// ---------------------------------------------------------------------------
__global__ void __launch_bounds__(256) interp_kernel(const float* __restrict__ V) {
    int p = blockIdx.x * 256 + threadIdx.x;
    float val = 0.0f;
    if (p < NPTS) {
        float vx = V[3 * p + 0], vy = V[3 * p + 1], vz = V[3 * p + 2];
        int ix0, ix1, iy0, iy1, iz0, iz1;
        float fx, fy, fz;
        corner_setup(vx, ix0, ix1, fx);
        corner_setup(vy, iy0, iy1, fy);
        corner_setup(vz, iz0, iz1, fz);
        float wx[2] = {1.0f - fx, fx};
        float wy[2] = {1.0f - fy, fy};
        float wz[2] = {1.0f - fz, fz};
        int ix[2] = {ix0, ix1}, iy[2] = {iy0, iy1}, iz[2] = {iz0, iz1};
#pragma unroll
        for (int c = 0; c < 8; c++) {
            int b0 = (c >> 2) & 1, b1 = (c >> 1) & 1, b2 = c & 1;
            int lin = (((ix[b0] << 8) | iy[b1]) << 8) | iz[b2];
            val += wx[b0] * wy[b1] * wz[b2] * __ldg(&gZ[lin]);
        }
    }
    __shared__ float red[256];
    red[threadIdx.x] = val;
    __syncthreads();
#pragma unroll
    for (int off = 128; off > 0; off >>= 1) {
        if (threadIdx.x < off) red[threadIdx.x] += red[threadIdx.x + off];
        __syncthreads();
    }
    if (threadIdx.x == 0) atomicAdd(&g_accum, (double)red[0]);
}

// ---------------------------------------------------------------------------
__global__ void __launch_bounds__(256) final_kernel(float4* __restrict__ out) {
    int idx = blockIdx.x * 256 + threadIdx.x;
    float mean = (float)(g_accum * (1.0 / (double)NPTS));
    float f0 = gZ[0] - mean;
    float sc = -0.5f / fabsf(f0);
    float4 v = *((const float4*)gZ + idx);
    v.x = (v.x - mean) * sc;
    v.y = (v.y - mean) * sc;
    v.z = (v.z - mean) * sc;
    v.w = (v.w - mean) * sc;
    out[idx] = v;
}

// ---------------------------------------------------------------------------
extern "C" void kernel_launch(void* const* d_in, const int* in_sizes, int n_in,
                              void* d_out, int out_size) {
    const float* V  = (const float*)d_in[0];
    const float* Np = (const float*)d_in[1];

    void *pA, *pX, *pY, *pW, *pZ, *pAcc;
    cudaGetSymbolAddress(&pA, gA);
    cudaGetSymbolAddress(&pX, gX);
    cudaGetSymbolAddress(&pY, gY);
    cudaGetSymbolAddress(&pW, gW);
    cudaGetSymbolAddress(&pZ, gZ);
    cudaGetSymbolAddress(&pAcc, g_accum);

    cudaMemsetAsync(pA, 0, (size_t)NVOX * sizeof(float2));
    cudaMemsetAsync(pZ, 0, (size_t)NVOX * sizeof(float));
    cudaMemsetAsync(pAcc, 0, sizeof(double));

    const int PB = (NPTS + 255) / 256;

    scatter_kernel<<<PB, 256>>>(V, Np);

    dim3 gHalf(17, 256);
    dim3 gHalf2(17, 256, 2);
    const int S1 = NH;
    const int O1 = 256 * NH;
    const int S0 = 256 * NH;
    const int O0 = NH;

    // x,y channels: axis-2 FFT + Hermitian split into compact gX, gY
    fft_axis2_split<<<8192, 256>>>((const float2*)pA, (float2*)pX, (float2*)pY);
    fft_strided_xy<<<gHalf2, 256>>>((float2*)pX, (float2*)pY, S1, O1);  // X,Y axis 1

    // z channel: R2C axis 2 -> compact gW, then axes 1, 0
    fft_axis2_r2c<<<4096, 256>>>((const float*)pZ, (float2*)pW);
    fft_strided_reg<-1><<<gHalf, 256>>>((float2*)pW, S1, O1);   // W axis 1
    fft_strided_reg<-1><<<gHalf, 256>>>((float2*)pW, S0, O0);   // W axis 0

    // fused: fwd axis-0 of X,Y + combine (gW streamed) + inverse axis-0 of Phi
    fused_axis0_combine<<<gHalf, 256>>>();

    // inverse axis 1, then C2R axis 2 into gZ
    fft_strided_reg<1><<<gHalf, 256>>>((float2*)pW, S1, O1);
    fft_axis2_c2r<<<4096, 256>>>((const float2*)pW, (float*)pZ);

    interp_kernel<<<PB, 256>>>(V);
    final_kernel<<<16384, 256>>>((float4*)d_out);
}

// round 17
// speedup vs baseline: 1.4221x; 1.0268x over previous
#include <cuda_runtime.h>
#include <math.h>

static constexpr int NPTS = 500000;
static constexpr int NVOX = 1 << 24;       // 256^3
static constexpr int NH   = 136;           // compact k2 width (17 chunks of 8)
static constexpr int NHVOX = 256 * 256 * NH;

__device__ float2 gA[NVOX];    // scatter target: ras_x + i*ras_y
__device__ float2 gX[NHVOX];   // N^x spectrum (axes 2 then 1), compact k2<=135
__device__ float2 gY[NHVOX];   // N^y spectrum, compact
__device__ float2 gW[NHVOX];   // N^z spectrum (axes 2,1) -> Phi -> partial inverse
__device__ float  gZ[NVOX];    // ras_z (real) in; phi (real) out
__device__ double g_accum;

// ---------------------------------------------------------------------------
__device__ __forceinline__ void corner_setup(float v, int& i0, int& i1, float& f) {
    float x  = v * 256.0f;
    float fl = floorf(x);
    i0 = (int)fl;
    f  = x - fl;
    i1 = (i0 + 1) & 255;
}

// ---------------------------------------------------------------------------
__global__ void __launch_bounds__(256) scatter_kernel(const float* __restrict__ V,
                                                      const float* __restrict__ N) {
    int p = blockIdx.x * 256 + threadIdx.x;
    if (p >= NPTS) return;
    float vx = __ldg(&V[3 * p + 0]), vy = __ldg(&V[3 * p + 1]), vz = __ldg(&V[3 * p + 2]);
    float nx = __ldg(&N[3 * p + 0]), ny = __ldg(&N[3 * p + 1]), nz = __ldg(&N[3 * p + 2]);

    int ix0, ix1, iy0, iy1, iz0, iz1;
    float fx, fy, fz;
    corner_setup(vx, ix0, ix1, fx);
    corner_setup(vy, iy0, iy1, fy);
    corner_setup(vz, iz0, iz1, fz);

    float wx[2] = {1.0f - fx, fx};
    float wy[2] = {1.0f - fy, fy};
    float wz[2] = {1.0f - fz, fz};
    int ix[2] = {ix0, ix1}, iy[2] = {iy0, iy1}, iz[2] = {iz0, iz1};

#pragma unroll
    for (int c = 0; c < 8; c++) {
        int b0 = (c >> 2) & 1, b1 = (c >> 1) & 1, b2 = c & 1;
        int lin = (((ix[b0] << 8) | iy[b1]) << 8) | iz[b2];
        float w = wx[b0] * wy[b1] * wz[b2];
        asm volatile("red.global.add.v2.f32 [%0], {%1, %2};"
                     :: "l"(&gA[lin]), "f"(w * nx), "f"(w * ny) : "memory");
        atomicAdd(&gZ[lin], w * nz);
    }
}

// ---------------------------------------------------------------------------
// Warp-level 256-pt FFT: 8 complex per thread.
// Input: reg j holds x[32*br3(j)+lane]. Output: lane holds X[j + 8*br5(lane)].
// ---------------------------------------------------------------------------
__device__ __forceinline__ void xstage(float (&ar)[8], float (&ai)[8], int lane, int h,
                                       float twr_in, float twi_in) {
    const bool up = (lane & h) != 0;
    const float s  = up ? -1.0f : 1.0f;
    const float tr = up ? twr_in : 1.0f;
    const float ti = up ? twi_in : 0.0f;
#pragma unroll
    for (int k = 0; k < 8; k++) {
        float orr = __shfl_xor_sync(0xffffffffu, ar[k], h);
        float ori = __shfl_xor_sync(0xffffffffu, ai[k], h);
        float dr = fmaf(s, ar[k], orr);
        float di = fmaf(s, ai[k], ori);
        ar[k] = dr * tr - di * ti;
        ai[k] = dr * ti + di * tr;
    }
}

template <int DIR>
__device__ __forceinline__ void warp_fft256_reg(float (&ar)[8], float (&ai)[8], int lane) {
    const float D = (float)DIR;
    const float C = 0.70710678118654752440f;
    float tr, ti;

#pragma unroll
    for (int p = 0; p < 8; p += 2) {
        tr = ar[p + 1]; ti = ai[p + 1];
        ar[p + 1] = ar[p] - tr;  ai[p + 1] = ai[p] - ti;
        ar[p] += tr;             ai[p] += ti;
    }
#pragma unroll
    for (int q = 0; q < 8; q += 4) {
        tr = ar[q + 2]; ti = ai[q + 2];
        ar[q + 2] = ar[q] - tr;  ai[q + 2] = ai[q] - ti;
        ar[q] += tr;             ai[q] += ti;
        tr = -D * ai[q + 3];     ti = D * ar[q + 3];
        ar[q + 3] = ar[q + 1] - tr;  ai[q + 3] = ai[q + 1] - ti;
        ar[q + 1] += tr;             ai[q + 1] += ti;
    }
    tr = ar[4]; ti = ai[4];
    ar[4] = ar[0] - tr; ai[4] = ai[0] - ti; ar[0] += tr; ai[0] += ti;
    tr = C * (ar[5] - D * ai[5]); ti = C * (ai[5] + D * ar[5]);
    ar[5] = ar[1] - tr; ai[5] = ai[1] - ti; ar[1] += tr; ai[1] += ti;
    tr = -D * ai[6]; ti = D * ar[6];
    ar[6] = ar[2] - tr; ai[6] = ai[2] - ti; ar[2] += tr; ai[2] += ti;
    tr = -C * (ar[7] + D * ai[7]); ti = C * (D * ar[7] - ai[7]);
    ar[7] = ar[3] - tr; ai[7] = ai[3] - ti; ar[3] += tr; ai[3] += ti;

    float w1r, w1i;
    __sincosf(D * 0.024543692606170259f * (float)lane, &w1i, &w1r);   // 2*pi/256
    float wr = w1r, wi = w1i;
#pragma unroll
    for (int k = 1; k < 8; k++) {
        tr = ar[k] * wr - ai[k] * wi;
        ai[k] = ar[k] * wi + ai[k] * wr;
        ar[k] = tr;
        if (k < 7) { float nr = wr * w1r - wi * w1i; wi = wr * w1i + wi * w1r; wr = nr; }
    }

    float s16r, s16i, s8r, s8i, s4r, s4i;
    __sincosf(D * 0.19634954084936207f * (float)(lane & 15), &s16i, &s16r);  // pi/16
    __sincosf(D * 0.39269908169872414f * (float)(lane & 7),  &s8i,  &s8r);   // pi/8
    __sincosf(D * 0.78539816339744831f * (float)(lane & 3),  &s4i,  &s4r);   // pi/4
    xstage(ar, ai, lane, 16, s16r, s16i);
    xstage(ar, ai, lane, 8,  s8r,  s8i);
    xstage(ar, ai, lane, 4,  s4r,  s4i);
    xstage(ar, ai, lane, 2, (lane & 1) ? 0.0f : 1.0f, (lane & 1) ? D : 0.0f);
    xstage(ar, ai, lane, 1, 1.0f, 0.0f);
}

// smem address map for a 256-entry line: addr(k) = 9*(k>>3) + (k&7)
__device__ __forceinline__ int lmap(int k) { return 9 * (k >> 3) + (k & 7); }

// ---------------------------------------------------------------------------
// A axis-2 pass + Hermitian channel split into compact gX, gY (k2 <= 135).
// ---------------------------------------------------------------------------
__global__ void __launch_bounds__(256) fft_axis2_split(const float2* __restrict__ A,
                                                       float2* __restrict__ X,
                                                       float2* __restrict__ Y) {
    __shared__ float s_re[8][288];
    __shared__ float s_im[8][288];
    int w = threadIdx.x >> 5, lane = threadIdx.x & 31;
    int line = blockIdx.x * 8 + w;
    int ibase = line * 256;
    int obase = line * NH;

    float ar[8], ai[8];
    const int br3[8] = {0, 4, 2, 6, 1, 5, 3, 7};
#pragma unroll
    for (int t = 0; t < 8; t++) {
        float2 v = A[ibase + 32 * br3[t] + lane];
        ar[t] = v.x; ai[t] = v.y;
    }
    warp_fft256_reg<-1>(ar, ai, lane);

    int m = (int)(__brev((unsigned)lane) >> 27);
#pragma unroll
    for (int t = 0; t < 8; t++) {
        s_re[w][9 * m + t] = ar[t];
        s_im[w][9 * m + t] = ai[t];
    }
    __syncwarp();

#pragma unroll
    for (int t = 0; t < 5; t++) {
        int k = lane + 32 * t;
        if (t < 4 || lane < 8) {
            int km = (256 - k) & 255;
            float ur = s_re[w][lmap(k)],  ui = s_im[w][lmap(k)];
            float vr = s_re[w][lmap(km)], vi = s_im[w][lmap(km)];
            X[obase + k] = make_float2(0.5f * (ur + vr),  0.5f * (ui - vi));
            Y[obase + k] = make_float2(0.5f * (ui + vi), -0.5f * (ur - vr));
        }
    }
}

// ---------------------------------------------------------------------------
// z-channel axis-2 forward R2C into compact gW.
// ---------------------------------------------------------------------------
__global__ void __launch_bounds__(256) fft_axis2_r2c(const float* __restrict__ in,
                                                     float2* __restrict__ g) {
    __shared__ float s_re[8][288];
    __shared__ float s_im[8][288];
    int w = threadIdx.x >> 5, lane = threadIdx.x & 31;
    int pj = blockIdx.x * 8 + w;
    int i0 = pj >> 7, j = pj & 127;
    int la = (i0 << 16) | (j << 9);
    int lb = la + 256;
    int oa = (i0 * 256 + 2 * j) * NH;
    int ob = oa + NH;

    float ar[8], ai[8];
    const int br3[8] = {0, 4, 2, 6, 1, 5, 3, 7};
#pragma unroll
    for (int t = 0; t < 8; t++) {
        int idx = 32 * br3[t] + lane;
        ar[t] = in[la + idx];
        ai[t] = in[lb + idx];
    }
    warp_fft256_reg<-1>(ar, ai, lane);

    int m = (int)(__brev((unsigned)lane) >> 27);
#pragma unroll
    for (int t = 0; t < 8; t++) {
        s_re[w][9 * m + t] = ar[t];
        s_im[w][9 * m + t] = ai[t];
    }
    __syncwarp();

#pragma unroll
    for (int t = 0; t < 5; t++) {
        int k = lane + 32 * t;
        if (t < 4 || lane < 8) {
            int km = (256 - k) & 255;
            float ur = s_re[w][lmap(k)],  ui = s_im[w][lmap(k)];
            float vr = s_re[w][lmap(km)], vi = s_im[w][lmap(km)];
            g[oa + k] = make_float2(0.5f * (ur + vr),  0.5f * (ui - vi));
            g[ob + k] = make_float2(0.5f * (ui + vi), -0.5f * (ur - vr));
        }
    }
}

// ---------------------------------------------------------------------------
// axis-2 inverse C2R: compact Hermitian lines -> real full-stride lines.
// ---------------------------------------------------------------------------
__global__ void __launch_bounds__(256) fft_axis2_c2r(const float2* __restrict__ g,
                                                     float* __restrict__ outr) {
    __shared__ float s_re[8][288];
    __shared__ float s_im[8][288];
    int w = threadIdx.x >> 5, lane = threadIdx.x & 31;
    int pj = blockIdx.x * 8 + w;
    int i0 = pj >> 7, j = pj & 127;
    int la = (i0 << 16) | (j << 9);
    int lb = la + 256;
    int oa = (i0 * 256 + 2 * j) * NH;
    int ob = oa + NH;

#pragma unroll
    for (int t = 0; t < 5; t++) {
        int k = lane + 32 * t;
        if (t < 4 || lane == 0) {             // k <= 128
            float2 Ha = g[oa + k];
            float2 Hb = g[ob + k];
            s_re[w][lmap(k)] = Ha.x - Hb.y;
            s_im[w][lmap(k)] = Ha.y + Hb.x;
            if (k >= 1 && k <= 127) {
                s_re[w][lmap(256 - k)] = Ha.x + Hb.y;
                s_im[w][lmap(256 - k)] = Hb.x - Ha.y;
            }
        }
    }
    __syncwarp();

    float ar[8], ai[8];
    const int br3[8] = {0, 4, 2, 6, 1, 5, 3, 7};
#pragma unroll
    for (int t = 0; t < 8; t++) {
        int idx = 32 * br3[t] + lane;
        ar[t] = s_re[w][lmap(idx)];
        ai[t] = s_im[w][lmap(idx)];
    }
    warp_fft256_reg<1>(ar, ai, lane);

    int obp = 8 * (int)(__brev((unsigned)lane) >> 27);
    float4* pa = (float4*)(outr + la + obp);
    float4* pb = (float4*)(outr + lb + obp);
    pa[0] = make_float4(ar[0], ar[1], ar[2], ar[3]);
    pa[1] = make_float4(ar[4], ar[5], ar[6], ar[7]);
    pb[0] = make_float4(ai[0], ai[1], ai[2], ai[3]);
    pb[1] = make_float4(ai[4], ai[5], ai[6], ai[7]);
}

// ---------------------------------------------------------------------------
// Strided-axis pass (compact volumes). blockIdx.y = outer, blockIdx.x = chunk.
// minBlocks=5 -> 51 regs -> 5 blocks/SM (occ 58%).
// ---------------------------------------------------------------------------
template <int DIR>
__global__ void __launch_bounds__(256, 5) fft_strided_reg(float2* __restrict__ g,
                                                          int S, int outerStride) {
    __shared__ float s_re[2304];
    __shared__ float s_im[2304];

    int tid  = threadIdx.x;
    int base = blockIdx.y * outerStride + blockIdx.x * 8;

#pragma unroll
    for (int it = 0; it < 8; it++) {
        int e = it * 256 + tid;
        int r = e >> 3, c = e & 7;
        float2 v = g[base + r * S + c];
        int a = 9 * r + (c ^ ((r >> 5) & 7));
        s_re[a] = v.x; s_im[a] = v.y;
    }
    __syncthreads();

    int w = tid >> 5, lane = tid & 31;
    float ar[8], ai[8];
    const int br3[8] = {0, 4, 2, 6, 1, 5, 3, 7};
#pragma unroll
    for (int j = 0; j < 8; j++) {
        int r = 32 * br3[j] + lane;
        int a = 9 * r + (w ^ ((r >> 5) & 7));
        ar[j] = s_re[a]; ai[j] = s_im[a];
    }

    warp_fft256_reg<DIR>(ar, ai, lane);
    __syncthreads();

    int k2 = (int)(__brev((unsigned)lane) >> 27);
#pragma unroll
    for (int k1 = 0; k1 < 8; k1++) {
        int r = k1 + 8 * k2;
        int a = 9 * r + (w ^ ((r >> 5) & 7));
        s_re[a] = ar[k1]; s_im[a] = ai[k1];
    }
    __syncthreads();

#pragma unroll
    for (int it = 0; it < 8; it++) {
        int e = it * 256 + tid;
        int r = e >> 3, c = e & 7;
        int a = 9 * r + (c ^ ((r >> 5) & 7));
        float2 v;
        v.x = s_re[a]; v.y = s_im[a];
        g[base + r * S + c] = v;
    }
}

// Dual-volume variant: identical body, blockIdx.z selects gX or gY (axis-1).
__global__ void __launch_bounds__(256, 5) fft_strided_xy(float2* __restrict__ X,
                                                         float2* __restrict__ Y,
                                                         int S, int outerStride) {
    __shared__ float s_re[2304];
    __shared__ float s_im[2304];
    float2* g = (blockIdx.z == 0) ? X : Y;

    int tid  = threadIdx.x;
    int base = blockIdx.y * outerStride + blockIdx.x * 8;

#pragma unroll
    for (int it = 0; it < 8; it++) {
        int e = it * 256 + tid;
        int r = e >> 3, c = e & 7;
        float2 v = g[base + r * S + c];
        int a = 9 * r + (c ^ ((r >> 5) & 7));
        s_re[a] = v.x; s_im[a] = v.y;
    }
    __syncthreads();

    int w = tid >> 5, lane = tid & 31;
    float ar[8], ai[8];
    const int br3[8] = {0, 4, 2, 6, 1, 5, 3, 7};
#pragma unroll
    for (int j = 0; j < 8; j++) {
        int r = 32 * br3[j] + lane;
        int a = 9 * r + (w ^ ((r >> 5) & 7));
        ar[j] = s_re[a]; ai[j] = s_im[a];
    }

    warp_fft256_reg<-1>(ar, ai, lane);
    __syncthreads();

    int k2 = (int)(__brev((unsigned)lane) >> 27);
#pragma unroll
    for (int k1 = 0; k1 < 8; k1++) {
        int r = k1 + 8 * k2;
        int a = 9 * r + (w ^ ((r >> 5) & 7));
        s_re[a] = ar[k1]; s_im[a] = ai[k1];
    }
    __syncthreads();

#pragma unroll
    for (int it = 0; it < 8; it++) {
        int e = it * 256 + tid;
        int r = e >> 3, c = e & 7;
        int a = 9 * r + (c ^ ((r >> 5) & 7));
        float2 v;
        v.x = s_re[a]; v.y = s_im[a];
        g[base + r * S + c] = v;
    }
}

// ---------------------------------------------------------------------------
// FUSED: forward axis-0 FFT of X^ and Y^ tiles + spectral combine (gW
// streamed) + inverse axis-0 FFT of Phi -> gW. minBlocks=5 (smem 36KB allows
// 6 blocks; regs were the limit at 64).
// ---------------------------------------------------------------------------
__global__ void __launch_bounds__(256, 5) fused_axis0_combine() {
    __shared__ float sX_re[2304], sX_im[2304];
    __shared__ float sY_re[2304], sY_im[2304];

    int tid  = threadIdx.x;
    int k1   = blockIdx.y;
    int t2   = blockIdx.x;
    int cbase = k1 * NH + t2 * 8;

#pragma unroll
    for (int it = 0; it < 8; it++) {
        int e = it * 256 + tid;
        int r = e >> 3, c = e & 7;
        int a = 9 * r + (c ^ ((r >> 5) & 7));
        int gi = r * (256 * NH) + cbase + c;
        float2 vx = gX[gi];
        sX_re[a] = vx.x; sX_im[a] = vx.y;
        float2 vy = gY[gi];
        sY_re[a] = vy.x; sY_im[a] = vy.y;
    }
    __syncthreads();

    int w = tid >> 5, lane = tid & 31;
    const int br3[8] = {0, 4, 2, 6, 1, 5, 3, 7};
    int k2r = (int)(__brev((unsigned)lane) >> 27);
    float ar[8], ai[8];

#pragma unroll
    for (int j = 0; j < 8; j++) {
        int r = 32 * br3[j] + lane;
        int a = 9 * r + (w ^ ((r >> 5) & 7));
        ar[j] = sX_re[a]; ai[j] = sX_im[a];
    }
    warp_fft256_reg<-1>(ar, ai, lane);
#pragma unroll
    for (int k = 0; k < 8; k++) {
        int r = k + 8 * k2r;
        int a = 9 * r + (w ^ ((r >> 5) & 7));
        sX_re[a] = ar[k]; sX_im[a] = ai[k];
    }
    __syncwarp();

#pragma unroll
    for (int j = 0; j < 8; j++) {
        int r = 32 * br3[j] + lane;
        int a = 9 * r + (w ^ ((r >> 5) & 7));
        ar[j] = sY_re[a]; ai[j] = sY_im[a];
    }
    warp_fft256_reg<-1>(ar, ai, lane);
#pragma unroll
    for (int k = 0; k < 8; k++) {
        int r = k + 8 * k2r;
        int a = 9 * r + (w ^ ((r >> 5) & 7));
        sY_re[a] = ar[k]; sY_im[a] = ai[k];
    }
    __syncthreads();

    float w1 = (float)(k1 - ((k1 >= 128) ? 256 : 0));
#pragma unroll
    for (int it = 0; it < 8; it++) {
        int e = it * 256 + tid;
        int r = e >> 3, c = e & 7;
        int a = 9 * r + (c ^ ((r >> 5) & 7));

        float Nxr = sX_re[a], Nxi = sX_im[a];
        float Nyr = sY_re[a], Nyi = sY_im[a];
        float2 Bz = gW[r * (256 * NH) + cbase + c];

        int k0 = r, k2 = 8 * t2 + c;
        float w0 = (float)(k0 - ((k0 >= 128) ? 256 : 0));
        float w2 = (float)(k2 - ((k2 >= 128) ? 256 : 0));

        float Dr = Nxr * w0 + Nyr * w1 + Bz.x * w2;
        float Di = Nxi * w0 + Nyi * w1 + Bz.y * w2;

        float s = w0 * w0 + w1 * w1 + w2 * w2;
        float G = expf(s * (-200.0f / 65536.0f));
        float denom = -39.478417604357434f * s + 1e-6f;
        float f = (6.283185307179586f * G / denom) * (1.0f / 16777216.0f);

        float pr = Di * f;
        float pi = -Dr * f;
        if ((r | k1 | t2 | c) == 0) { pr = 0.0f; pi = 0.0f; }

        sX_re[a] = pr; sX_im[a] = pi;
    }
    __syncthreads();

#pragma unroll
    for (int j = 0; j < 8; j++) {
        int r = 32 * br3[j] + lane;
        int a = 9 * r + (w ^ ((r >> 5) & 7));
        ar[j] = sX_re[a]; ai[j] = sX_im[a];
    }
    warp_fft256_reg<1>(ar, ai, lane);
    __syncthreads();
#pragma unroll
    for (int j = 0; j < 8; j++) {
        int r = j + 8 * k2r;
        int a = 9 * r + (w ^ ((r >> 5) & 7));
        sX_re[a] = ar[j]; sX_im[a] = ai[j];
    }
    __syncthreads();

#pragma unroll
    for (int it = 0; it < 8; it++) {
        int e = it * 256 + tid;
        int r = e >> 3, c = e & 7;
        int a = 9 * r + (c ^ ((r >> 5) & 7));
        float2 v;
        v.x = sX_re[a]; v.y = sX_im[a];
        gW[r * (256 * NH) + cbase + c] = v;
    }
}

// ---------------------------------------------------------------------------
__global__ void __launch_bounds__(256) interp_kernel(const float* __restrict__ V) {
    int p = blockIdx.x * 256 + threadIdx.x;
    float val = 0.0f;
    if (p < NPTS) {
        float vx = V[3 * p + 0], vy = V[3 * p + 1], vz = V[3 * p + 2];
        int ix0, ix1, iy0, iy1, iz0, iz1;
        float fx, fy, fz;
        corner_setup(vx, ix0, ix1, fx);
        corner_setup(vy, iy0, iy1, fy);
        corner_setup(vz, iz0, iz1, fz);
        float wx[2] = {1.0f - fx, fx};
        float wy[2] = {1.0f - fy, fy};
        float wz[2] = {1.0f - fz, fz};
        int ix[2] = {ix0, ix1}, iy[2] = {iy0, iy1}, iz[2] = {iz0, iz1};
#pragma unroll
        for (int c = 0; c < 8; c++) {
            int b0 = (c >> 2) & 1, b1 = (c >> 1) & 1, b2 = c & 1;
            int lin = (((ix[b0] << 8) | iy[b1]) << 8) | iz[b2];
            val += wx[b0] * wy[b1] * wz[b2] * __ldg(&gZ[lin]);
        }
    }
    // warp-shuffle reduction, then one smem round across the 8 warps
#pragma unroll
    for (int off = 16; off > 0; off >>= 1)
        val += __shfl_xor_sync(0xffffffffu, val, off);
    __shared__ float red[8];
    int w = threadIdx.x >> 5, lane = threadIdx.x & 31;
    if (lane == 0) red[w] = val;
    __syncthreads();
    if (threadIdx.x == 0) {
        float s = 0.0f;
#pragma unroll
        for (int i = 0; i < 8; i++) s += red[i];
        atomicAdd(&g_accum, (double)s);
    }
}

// ---------------------------------------------------------------------------
__global__ void __launch_bounds__(256) final_kernel(float4* __restrict__ out) {
    int idx = blockIdx.x * 256 + threadIdx.x;
    float mean = (float)(g_accum * (1.0 / (double)NPTS));
    float f0 = gZ[0] - mean;
    float sc = -0.5f / fabsf(f0);
    float4 v = *((const float4*)gZ + idx);
    v.x = (v.x - mean) * sc;
    v.y = (v.y - mean) * sc;
    v.z = (v.z - mean) * sc;
    v.w = (v.w - mean) * sc;
    out[idx] = v;
}

// ---------------------------------------------------------------------------
extern "C" void kernel_launch(void* const* d_in, const int* in_sizes, int n_in,
                              void* d_out, int out_size) {
    const float* V  = (const float*)d_in[0];
    const float* Np = (const float*)d_in[1];

    void *pA, *pX, *pY, *pW, *pZ, *pAcc;
    cudaGetSymbolAddress(&pA, gA);
    cudaGetSymbolAddress(&pX, gX);
    cudaGetSymbolAddress(&pY, gY);
    cudaGetSymbolAddress(&pW, gW);
    cudaGetSymbolAddress(&pZ, gZ);
    cudaGetSymbolAddress(&pAcc, g_accum);

    cudaMemsetAsync(pA, 0, (size_t)NVOX * sizeof(float2));
    cudaMemsetAsync(pZ, 0, (size_t)NVOX * sizeof(float));
    cudaMemsetAsync(pAcc, 0, sizeof(double));

    const int PB = (NPTS + 255) / 256;

    scatter_kernel<<<PB, 256>>>(V, Np);

    dim3 gHalf(17, 256);
    dim3 gHalf2(17, 256, 2);
    const int S1 = NH;
    const int O1 = 256 * NH;
    const int S0 = 256 * NH;
    const int O0 = NH;

    // x,y channels: axis-2 FFT + Hermitian split into compact gX, gY
    fft_axis2_split<<<8192, 256>>>((const float2*)pA, (float2*)pX, (float2*)pY);
    fft_strided_xy<<<gHalf2, 256>>>((float2*)pX, (float2*)pY, S1, O1);  // X,Y axis 1

    // z channel: R2C axis 2 -> compact gW, then axes 1, 0
    fft_axis2_r2c<<<4096, 256>>>((const float*)pZ, (float2*)pW);
    fft_strided_reg<-1><<<gHalf, 256>>>((float2*)pW, S1, O1);   // W axis 1
    fft_strided_reg<-1><<<gHalf, 256>>>((float2*)pW, S0, O0);   // W axis 0

    // fused: fwd axis-0 of X,Y + combine (gW streamed) + inverse axis-0 of Phi
    fused_axis0_combine<<<gHalf, 256>>>();

    // inverse axis 1, then C2R axis 2 into gZ
    fft_strided_reg<1><<<gHalf, 256>>>((float2*)pW, S1, O1);
    fft_axis2_c2r<<<4096, 256>>>((const float2*)pW, (float*)pZ);

    interp_kernel<<<PB, 256>>>(V);
    final_kernel<<<16384, 256>>>((float4*)d_out);
}